// round 10
// baseline (speedup 1.0000x reference)
#include <cuda_runtime.h>
#include <cuda_fp16.h>
#include <cstdint>
#include <type_traits>

#define N_NODES 20000
#define MAXC 256
#define MAXE 360000

// ---------------- scratch ----------------
__device__ int    g_indeg[N_NODES];
__device__ int    g_fill[N_NODES];
__device__ int    g_row_off[N_NODES];
__device__ float  g_dis[N_NODES];
__device__ int    g_csr_src[MAXE];
__device__ float  g_csr_w[MAXE];                 // dis[src] per edge
__device__ __half g_h[(size_t)N_NODES * MAXC];   // GEMM output (fp16, gathered)
__device__ __half g_t[(size_t)N_NODES * MAXC];   // layer activation (fp16)

// ---------------- CSR build ----------------
__global__ void zero_counts_kernel() {
    int i = blockIdx.x * blockDim.x + threadIdx.x;
    if (i < N_NODES) { g_indeg[i] = 0; g_fill[i] = 0; }
}

__global__ void count_kernel(const int* __restrict__ ei, int E) {
    int e = blockIdx.x * blockDim.x + threadIdx.x;
    if (e < E) atomicAdd(&g_indeg[ei[E + e]], 1);
}

// warp-shuffle exclusive scan of g_indeg -> g_row_off; also computes g_dis
__global__ void scan_kernel() {
    __shared__ int wsum[32];
    const int CH = 20;
    int t = threadIdx.x;              // 1024 threads
    int lane = t & 31, wid = t >> 5;
    int base = t * CH;
    int local[CH];
    int s = 0;
    #pragma unroll
    for (int i = 0; i < CH; i++) {
        int idx = base + i;
        int v = (idx < N_NODES) ? g_indeg[idx] : 0;
        local[i] = v;
        s += v;
    }
    int v = s;
    #pragma unroll
    for (int off = 1; off < 32; off <<= 1) {
        int n = __shfl_up_sync(0xffffffffu, v, off);
        if (lane >= off) v += n;
    }
    if (lane == 31) wsum[wid] = v;
    __syncthreads();
    if (wid == 0) {
        int w = wsum[lane];
        #pragma unroll
        for (int off = 1; off < 32; off <<= 1) {
            int n = __shfl_up_sync(0xffffffffu, w, off);
            if (lane >= off) w += n;
        }
        wsum[lane] = w;
    }
    __syncthreads();
    int warpoff = (wid == 0) ? 0 : wsum[wid - 1];
    int run = warpoff + v - s;
    #pragma unroll
    for (int i = 0; i < CH; i++) {
        int idx = base + i;
        if (idx < N_NODES) {
            g_row_off[idx] = run;
            run += local[i];
            g_dis[idx] = rsqrtf((float)local[i] + 1.0f);   // +1 self-loop
        }
    }
}

__global__ void fill_kernel(const int* __restrict__ ei, int E) {
    int e = blockIdx.x * blockDim.x + threadIdx.x;
    if (e < E) {
        int s = ei[e];
        int d = ei[E + e];
        int pos = g_row_off[d] + atomicAdd(&g_fill[d], 1);
        g_csr_src[pos] = s;
        g_csr_w[pos] = g_dis[s];
    }
}

// ---------------- FP16 tensor-core GEMM (m16n8k16, fp32 accum, BK=32) ----------------
// Ch[M,N] = half(A[M,K] @ B[K,N]); A fp32 or fp16, B(weights) fp32.
template<typename AT>
__global__ void gemm_f16_kernel(const AT* __restrict__ A, const float* __restrict__ B,
                                __half* __restrict__ Ch, int M, int N, int K) {
    const int BM = 128, BN = 64, BK = 32;
    __shared__ __half2 As[2][BM][20];   // [m][j] j=half2 idx 0..15, stride 20 words
    __shared__ __half  Bs[2][BN][40];   // [n][k] k=0..31, stride 40 halves (20 words)

    int tid = threadIdx.x;
    int lane = tid & 31;
    int wid = tid >> 5;
    int warp_m = wid & 3;     // 0..3 -> 32-row slab
    int warp_n = wid >> 2;    // 0..1 -> 32-col slab
    int brow = blockIdx.y * BM;
    int bcol = blockIdx.x * BN;

    int g = lane >> 2;        // 0..7
    int tg = lane & 3;        // 0..3

    float acc[2][4][4];
    #pragma unroll
    for (int i = 0; i < 2; i++)
        #pragma unroll
        for (int j = 0; j < 4; j++)
            #pragma unroll
            for (int q = 0; q < 4; q++) acc[i][j][q] = 0.0f;

    __half2 ra[8];
    __half  rbv[8];
    const __half2 zero2 = __floats2half2_rn(0.f, 0.f);

    // ---- prologue: tile 0 ----
    #pragma unroll
    for (int i = 0; i < 8; i++) {            // A: 128 rows x 16 half2
        int lin = tid + i * 256;
        int m = lin >> 4, j = lin & 15;
        int gr = brow + m;
        __half2 v;
        if constexpr (std::is_same<AT, float>::value) {
            float2 f = (gr < M) ? *(const float2*)&A[(size_t)gr * K + 2 * j]
                                : make_float2(0.f, 0.f);
            v = __floats2half2_rn(f.x, f.y);
        } else {
            v = (gr < M) ? *(const __half2*)&A[(size_t)gr * K + 2 * j] : zero2;
        }
        As[0][m][j] = v;
    }
    #pragma unroll
    for (int i = 0; i < 8; i++) {            // B: 32 k-rows x 64 cols, transposed
        int lin = tid + i * 256;
        int k = lin >> 6, n = lin & 63;
        Bs[0][n][k] = __float2half_rn(B[(size_t)k * N + bcol + n]);
    }
    __syncthreads();

    int KT = K / BK;
    int cur = 0;
    for (int kt = 0; kt < KT; kt++) {
        bool more = (kt + 1 < KT);
        if (more) {
            int k0n = (kt + 1) * BK;
            #pragma unroll
            for (int i = 0; i < 8; i++) {
                int lin = tid + i * 256;
                int m = lin >> 4, j = lin & 15;
                int gr = brow + m;
                if constexpr (std::is_same<AT, float>::value) {
                    float2 f = (gr < M) ? *(const float2*)&A[(size_t)gr * K + k0n + 2 * j]
                                        : make_float2(0.f, 0.f);
                    ra[i] = __floats2half2_rn(f.x, f.y);
                } else {
                    ra[i] = (gr < M) ? *(const __half2*)&A[(size_t)gr * K + k0n + 2 * j] : zero2;
                }
            }
            #pragma unroll
            for (int i = 0; i < 8; i++) {
                int lin = tid + i * 256;
                int k = lin >> 6, n = lin & 63;
                rbv[i] = __float2half_rn(B[(size_t)(k0n + k) * N + bcol + n]);
            }
        }

        // two m16n8k16 k-steps per tile
        #pragma unroll
        for (int ks = 0; ks < 2; ks++) {
            int jb = ks * 8;   // half2 base within row
            uint32_t af[2][4], bf[4][2];
            #pragma unroll
            for (int mt = 0; mt < 2; mt++) {
                int r0 = warp_m * 32 + mt * 16 + g;
                af[mt][0] = *(const uint32_t*)&As[cur][r0][jb + tg];
                af[mt][1] = *(const uint32_t*)&As[cur][r0 + 8][jb + tg];
                af[mt][2] = *(const uint32_t*)&As[cur][r0][jb + tg + 4];
                af[mt][3] = *(const uint32_t*)&As[cur][r0 + 8][jb + tg + 4];
            }
            #pragma unroll
            for (int nt = 0; nt < 4; nt++) {
                int c0 = warp_n * 32 + nt * 8 + g;
                bf[nt][0] = *(const uint32_t*)&Bs[cur][c0][2 * jb + 2 * tg];
                bf[nt][1] = *(const uint32_t*)&Bs[cur][c0][2 * jb + 2 * tg + 8];
            }
            #pragma unroll
            for (int mt = 0; mt < 2; mt++)
                #pragma unroll
                for (int nt = 0; nt < 4; nt++) {
                    asm volatile(
                        "mma.sync.aligned.m16n8k16.row.col.f32.f16.f16.f32 "
                        "{%0,%1,%2,%3}, {%4,%5,%6,%7}, {%8,%9}, {%0,%1,%2,%3};"
                        : "+f"(acc[mt][nt][0]), "+f"(acc[mt][nt][1]),
                          "+f"(acc[mt][nt][2]), "+f"(acc[mt][nt][3])
                        : "r"(af[mt][0]), "r"(af[mt][1]), "r"(af[mt][2]), "r"(af[mt][3]),
                          "r"(bf[nt][0]), "r"(bf[nt][1]));
                }
        }

        if (more) {
            int nxt = cur ^ 1;
            #pragma unroll
            for (int i = 0; i < 8; i++) {
                int lin = tid + i * 256;
                int m = lin >> 4, j = lin & 15;
                As[nxt][m][j] = ra[i];
            }
            #pragma unroll
            for (int i = 0; i < 8; i++) {
                int lin = tid + i * 256;
                int k = lin >> 6, n = lin & 63;
                Bs[nxt][n][k] = rbv[i];
            }
            __syncthreads();
            cur = nxt;
        }
    }

    // epilogue: fp16 store, (c0,c1)/(c2,c3) as half2
    #pragma unroll
    for (int mt = 0; mt < 2; mt++) {
        int r0 = brow + warp_m * 32 + mt * 16 + g;
        int r1 = r0 + 8;
        #pragma unroll
        for (int nt = 0; nt < 4; nt++) {
            int cc = bcol + warp_n * 32 + nt * 8 + 2 * tg;
            if (r0 < M) {
                __half2 v = __floats2half2_rn(acc[mt][nt][0], acc[mt][nt][1]);
                *(__half2*)&Ch[(size_t)r0 * N + cc] = v;
            }
            if (r1 < M) {
                __half2 v = __floats2half2_rn(acc[mt][nt][2], acc[mt][nt][3]);
                *(__half2*)&Ch[(size_t)r1 * N + cc] = v;
            }
        }
    }
}

// ---------------- fused aggregate + self-loop + bias (+relu) ----------------
// h unscaled fp16; out[d] = relu(dis[d]*(sum_s dis[s]*h[s] + dis[d]*h[d]) + b)
__device__ __forceinline__ void fma8(float* acc, uint4 v, float w) {
    float2 f0 = __half22float2(*(__half2*)&v.x);
    float2 f1 = __half22float2(*(__half2*)&v.y);
    float2 f2 = __half22float2(*(__half2*)&v.z);
    float2 f3 = __half22float2(*(__half2*)&v.w);
    acc[0] = fmaf(f0.x, w, acc[0]); acc[1] = fmaf(f0.y, w, acc[1]);
    acc[2] = fmaf(f1.x, w, acc[2]); acc[3] = fmaf(f1.y, w, acc[3]);
    acc[4] = fmaf(f2.x, w, acc[4]); acc[5] = fmaf(f2.y, w, acc[5]);
    acc[6] = fmaf(f3.x, w, acc[6]); acc[7] = fmaf(f3.y, w, acc[7]);
}

template<int C, bool RELU, typename OUTT>
__global__ void aggregate_kernel(const __half* __restrict__ h,
                                 const float* __restrict__ bias,
                                 OUTT* __restrict__ out) {
    constexpr int TPN = C / 8;            // lanes per node (uint4 = 8 halves)
    constexpr int NPB = 128 / TPN;        // nodes per block
    int local = threadIdx.x / TPN;
    int c8 = threadIdx.x % TPN;
    int node = blockIdx.x * NPB + local;
    if (node >= N_NODES) return;

    const uint4* h8 = (const uint4*)h;
    const size_t S = C / 8;
    float d = g_dis[node];

    float acc[8] = {};
    fma8(acc, __ldg(&h8[(size_t)node * S + c8]), d);   // self-loop: dis[d]*h[d]

    int beg = g_row_off[node];
    int end = beg + g_indeg[node];
    int p = beg;
    for (; p + 4 <= end; p += 4) {
        int s0 = g_csr_src[p],   s1 = g_csr_src[p+1];
        int s2 = g_csr_src[p+2], s3 = g_csr_src[p+3];
        float w0 = g_csr_w[p],   w1 = g_csr_w[p+1];
        float w2 = g_csr_w[p+2], w3 = g_csr_w[p+3];
        uint4 v0 = __ldg(&h8[(size_t)s0 * S + c8]);
        uint4 v1 = __ldg(&h8[(size_t)s1 * S + c8]);
        uint4 v2 = __ldg(&h8[(size_t)s2 * S + c8]);
        uint4 v3 = __ldg(&h8[(size_t)s3 * S + c8]);
        fma8(acc, v0, w0); fma8(acc, v1, w1); fma8(acc, v2, w2); fma8(acc, v3, w3);
    }
    for (; p < end; ++p)
        fma8(acc, __ldg(&h8[(size_t)g_csr_src[p] * S + c8]), g_csr_w[p]);

    int colb = c8 * 8;
    float4 b0 = __ldg(&((const float4*)bias)[c8 * 2]);
    float4 b1 = __ldg(&((const float4*)bias)[c8 * 2 + 1]);
    float r[8];
    r[0] = fmaf(d, acc[0], b0.x); r[1] = fmaf(d, acc[1], b0.y);
    r[2] = fmaf(d, acc[2], b0.z); r[3] = fmaf(d, acc[3], b0.w);
    r[4] = fmaf(d, acc[4], b1.x); r[5] = fmaf(d, acc[5], b1.y);
    r[6] = fmaf(d, acc[6], b1.z); r[7] = fmaf(d, acc[7], b1.w);
    if (RELU) {
        #pragma unroll
        for (int i = 0; i < 8; i++) r[i] = fmaxf(r[i], 0.0f);
    }
    if constexpr (std::is_same<OUTT, __half>::value) {
        __half2 p0 = __floats2half2_rn(r[0], r[1]);
        __half2 p1 = __floats2half2_rn(r[2], r[3]);
        __half2 p2 = __floats2half2_rn(r[4], r[5]);
        __half2 p3 = __floats2half2_rn(r[6], r[7]);
        uint4 u;
        u.x = *(uint32_t*)&p0; u.y = *(uint32_t*)&p1;
        u.z = *(uint32_t*)&p2; u.w = *(uint32_t*)&p3;
        *(uint4*)&out[(size_t)node * C + colb] = u;
    } else {
        float4 r0 = make_float4(r[0], r[1], r[2], r[3]);
        float4 r1 = make_float4(r[4], r[5], r[6], r[7]);
        *(float4*)&out[(size_t)node * C + colb]     = r0;
        *(float4*)&out[(size_t)node * C + colb + 4] = r1;
    }
}

// ---------------- driver ----------------
static inline int cdiv(long long a, long long b) { return (int)((a + b - 1) / b); }

extern "C" void kernel_launch(void* const* d_in, const int* in_sizes, int n_in,
                              void* d_out, int out_size) {
    const float* x  = (const float*)d_in[0];
    const float* W1 = (const float*)d_in[1];
    const float* b1 = (const float*)d_in[2];
    const float* W2 = (const float*)d_in[3];
    const float* b2 = (const float*)d_in[4];
    const float* W3 = (const float*)d_in[5];
    const float* b3 = (const float*)d_in[6];
    const int*   ei = (const int*)d_in[7];   // int32 (JAX default dtype demotion)
    int E = in_sizes[7] / 2;
    float* out = (float*)d_out;

    __half *h, *t;
    cudaGetSymbolAddress((void**)&h, g_h);
    cudaGetSymbolAddress((void**)&t, g_t);

    // infrastructure handles (created on the eager correctness call, not during capture)
    static cudaStream_t s2 = [] {
        cudaStream_t s; cudaStreamCreateWithFlags(&s, cudaStreamNonBlocking); return s;
    }();
    static cudaEvent_t eFork = [] {
        cudaEvent_t e; cudaEventCreateWithFlags(&e, cudaEventDisableTiming); return e;
    }();
    static cudaEvent_t eJoin = [] {
        cudaEvent_t e; cudaEventCreateWithFlags(&e, cudaEventDisableTiming); return e;
    }();

    const int TPB = 256;

    // ---- fork: ENTIRE CSR build on s2, hidden under layer-1 GEMM ----
    cudaEventRecord(eFork, 0);
    cudaStreamWaitEvent(s2, eFork, 0);
    zero_counts_kernel<<<cdiv(N_NODES, TPB), TPB, 0, s2>>>();
    count_kernel<<<cdiv(E, TPB), TPB, 0, s2>>>(ei, E);
    scan_kernel<<<1, 1024, 0, s2>>>();
    fill_kernel<<<cdiv(E, TPB), TPB, 0, s2>>>(ei, E);
    cudaEventRecord(eJoin, s2);

    // ---- layer 1: 256 -> 256, relu ----
    {
        dim3 grid(256 / 64, cdiv(N_NODES, 128));
        gemm_f16_kernel<float><<<grid, 256>>>(x, W1, h, N_NODES, 256, 256);
        cudaStreamWaitEvent(0, eJoin, 0);
        aggregate_kernel<256, true, __half><<<cdiv(N_NODES, 4), 128>>>(h, b1, t);
    }
    // ---- layer 2: 256 -> 128, relu ----
    {
        dim3 grid(128 / 64, cdiv(N_NODES, 128));
        gemm_f16_kernel<__half><<<grid, 256>>>(t, W2, h, N_NODES, 128, 256);
        aggregate_kernel<128, true, __half><<<cdiv(N_NODES, 8), 128>>>(h, b2, t);
    }
    // ---- layer 3: 128 -> 64, no relu ----
    {
        dim3 grid(64 / 64, cdiv(N_NODES, 128));
        gemm_f16_kernel<__half><<<grid, 256>>>(t, W3, h, N_NODES, 64, 128);
        aggregate_kernel<64, false, float><<<cdiv(N_NODES, 16), 128>>>(h, b3, out);
    }
}

// round 11
// speedup vs baseline: 1.0528x; 1.0528x over previous
#include <cuda_runtime.h>
#include <cuda_fp16.h>
#include <cstdint>

#define N_NODES 20000
#define MAXC 256
#define MAXE 360000

// ---------------- scratch ----------------
__device__ int    g_indeg[N_NODES];
__device__ int    g_fill[N_NODES];
__device__ int    g_row_off[N_NODES];
__device__ float  g_dis[N_NODES];
__device__ int    g_csr_src[MAXE];
__device__ float  g_csr_w[MAXE];                 // dis[src] per edge
__device__ __half g_h[(size_t)N_NODES * MAXC];   // GEMM output (fp16, unscaled)
__device__ float  g_t[(size_t)N_NODES * MAXC];   // layer activation (fp32)

// ---------------- CSR build ----------------
__global__ void zero_counts_kernel() {
    int i = blockIdx.x * blockDim.x + threadIdx.x;
    if (i < N_NODES) { g_indeg[i] = 0; g_fill[i] = 0; }
}

__global__ void count_kernel(const int* __restrict__ ei, int E) {
    int e = blockIdx.x * blockDim.x + threadIdx.x;
    if (e < E) atomicAdd(&g_indeg[ei[E + e]], 1);
}

// warp-shuffle exclusive scan of g_indeg -> g_row_off; also computes g_dis
__global__ void scan_kernel() {
    __shared__ int wsum[32];
    const int CH = 20;
    int t = threadIdx.x;              // 1024 threads
    int lane = t & 31, wid = t >> 5;
    int base = t * CH;
    int local[CH];
    int s = 0;
    #pragma unroll
    for (int i = 0; i < CH; i++) {
        int idx = base + i;
        int v = (idx < N_NODES) ? g_indeg[idx] : 0;
        local[i] = v;
        s += v;
    }
    int v = s;
    #pragma unroll
    for (int off = 1; off < 32; off <<= 1) {
        int n = __shfl_up_sync(0xffffffffu, v, off);
        if (lane >= off) v += n;
    }
    if (lane == 31) wsum[wid] = v;
    __syncthreads();
    if (wid == 0) {
        int w = wsum[lane];
        #pragma unroll
        for (int off = 1; off < 32; off <<= 1) {
            int n = __shfl_up_sync(0xffffffffu, w, off);
            if (lane >= off) w += n;
        }
        wsum[lane] = w;
    }
    __syncthreads();
    int warpoff = (wid == 0) ? 0 : wsum[wid - 1];
    int run = warpoff + v - s;
    #pragma unroll
    for (int i = 0; i < CH; i++) {
        int idx = base + i;
        if (idx < N_NODES) {
            g_row_off[idx] = run;
            run += local[i];
            g_dis[idx] = rsqrtf((float)local[i] + 1.0f);   // +1 self-loop
        }
    }
}

__global__ void fill_kernel(const int* __restrict__ ei, int E) {
    int e = blockIdx.x * blockDim.x + threadIdx.x;
    if (e < E) {
        int s = ei[e];
        int d = ei[E + e];
        int pos = g_row_off[d] + atomicAdd(&g_fill[d], 1);
        g_csr_src[pos] = s;
        g_csr_w[pos] = g_dis[s];
    }
}

// ---------------- FP16 tensor-core GEMM (m16n8k16, fp32 accum, BK=16) ----------------
// Ch[M,N] = half(A[M,K] @ B[K,N]); A,B fp32 in, converted to fp16 tiles.
__global__ void gemm_f16_kernel(const float* __restrict__ A, const float* __restrict__ B,
                                __half* __restrict__ Ch, int M, int N, int K) {
    const int BM = 128, BN = 64, BK = 16;
    // A: half2 [m][k/2], stride 9 words (8 half2 + 1 pad)
    __shared__ __half2 As[2][BM][9];
    // B: half [n][k], stride 18 halves (16 + 2 pad = 9 words)
    __shared__ __half  Bs[2][BN][18];

    int tid = threadIdx.x;
    int lane = tid & 31;
    int wid = tid >> 5;
    int warp_m = wid & 3;     // 0..3 -> 32-row slab
    int warp_n = wid >> 2;    // 0..1 -> 32-col slab
    int brow = blockIdx.y * BM;
    int bcol = blockIdx.x * BN;

    int g = lane >> 2;        // 0..7
    int tg = lane & 3;        // 0..3

    float acc[2][4][4];
    #pragma unroll
    for (int i = 0; i < 2; i++)
        #pragma unroll
        for (int j = 0; j < 4; j++)
            #pragma unroll
            for (int q = 0; q < 4; q++) acc[i][j][q] = 0.0f;

    __half2 ra[4];
    __half  rbv[4];

    // ---- prologue: tile 0 ----
    #pragma unroll
    for (int i = 0; i < 4; i++) {            // A: 128 rows x 8 half2
        int lin = tid + i * 256;
        int m = lin >> 3, j = lin & 7;
        int gr = brow + m;
        float2 f = (gr < M) ? *(const float2*)&A[(size_t)gr * K + 2 * j]
                            : make_float2(0.f, 0.f);
        As[0][m][j] = __floats2half2_rn(f.x, f.y);
    }
    #pragma unroll
    for (int i = 0; i < 4; i++) {            // B: 16 k-rows x 64 cols, transposed store
        int lin = tid + i * 256;
        int k = lin >> 6, n = lin & 63;
        Bs[0][n][k] = __float2half_rn(B[(size_t)k * N + bcol + n]);
    }
    __syncthreads();

    int KT = K / BK;
    int cur = 0;
    for (int kt = 0; kt < KT; kt++) {
        bool more = (kt + 1 < KT);
        if (more) {
            int k0n = (kt + 1) * BK;
            #pragma unroll
            for (int i = 0; i < 4; i++) {
                int lin = tid + i * 256;
                int m = lin >> 3, j = lin & 7;
                int gr = brow + m;
                float2 f = (gr < M) ? *(const float2*)&A[(size_t)gr * K + k0n + 2 * j]
                                    : make_float2(0.f, 0.f);
                ra[i] = __floats2half2_rn(f.x, f.y);
            }
            #pragma unroll
            for (int i = 0; i < 4; i++) {
                int lin = tid + i * 256;
                int k = lin >> 6, n = lin & 63;
                rbv[i] = __float2half_rn(B[(size_t)(k0n + k) * N + bcol + n]);
            }
        }

        // one m16n8k16 k-step per tile
        uint32_t af[2][4], bf[4][2];
        #pragma unroll
        for (int mt = 0; mt < 2; mt++) {
            int r0 = warp_m * 32 + mt * 16 + g;
            af[mt][0] = *(const uint32_t*)&As[cur][r0][tg];
            af[mt][1] = *(const uint32_t*)&As[cur][r0 + 8][tg];
            af[mt][2] = *(const uint32_t*)&As[cur][r0][tg + 4];
            af[mt][3] = *(const uint32_t*)&As[cur][r0 + 8][tg + 4];
        }
        #pragma unroll
        for (int nt = 0; nt < 4; nt++) {
            int c0 = warp_n * 32 + nt * 8 + g;
            bf[nt][0] = *(const uint32_t*)&Bs[cur][c0][2 * tg];
            bf[nt][1] = *(const uint32_t*)&Bs[cur][c0][2 * tg + 8];
        }
        #pragma unroll
        for (int mt = 0; mt < 2; mt++)
            #pragma unroll
            for (int nt = 0; nt < 4; nt++) {
                asm volatile(
                    "mma.sync.aligned.m16n8k16.row.col.f32.f16.f16.f32 "
                    "{%0,%1,%2,%3}, {%4,%5,%6,%7}, {%8,%9}, {%0,%1,%2,%3};"
                    : "+f"(acc[mt][nt][0]), "+f"(acc[mt][nt][1]),
                      "+f"(acc[mt][nt][2]), "+f"(acc[mt][nt][3])
                    : "r"(af[mt][0]), "r"(af[mt][1]), "r"(af[mt][2]), "r"(af[mt][3]),
                      "r"(bf[nt][0]), "r"(bf[nt][1]));
            }

        if (more) {
            int nxt = cur ^ 1;
            #pragma unroll
            for (int i = 0; i < 4; i++) {
                int lin = tid + i * 256;
                int m = lin >> 3, j = lin & 7;
                As[nxt][m][j] = ra[i];
            }
            #pragma unroll
            for (int i = 0; i < 4; i++) {
                int lin = tid + i * 256;
                int k = lin >> 6, n = lin & 63;
                Bs[nxt][n][k] = rbv[i];
            }
            __syncthreads();
            cur = nxt;
        }
    }

    // epilogue: fp16 store, (c0,c1)/(c2,c3) as half2
    #pragma unroll
    for (int mt = 0; mt < 2; mt++) {
        int r0 = brow + warp_m * 32 + mt * 16 + g;
        int r1 = r0 + 8;
        #pragma unroll
        for (int nt = 0; nt < 4; nt++) {
            int cc = bcol + warp_n * 32 + nt * 8 + 2 * tg;
            if (r0 < M) {
                __half2 v = __floats2half2_rn(acc[mt][nt][0], acc[mt][nt][1]);
                *(__half2*)&Ch[(size_t)r0 * N + cc] = v;
            }
            if (r1 < M) {
                __half2 v = __floats2half2_rn(acc[mt][nt][2], acc[mt][nt][3]);
                *(__half2*)&Ch[(size_t)r1 * N + cc] = v;
            }
        }
    }
}

// ---------------- fused aggregate + self-loop + bias (+relu) ----------------
// h unscaled fp16; out[d] = relu(dis[d]*(sum_s dis[s]*h[s] + dis[d]*h[d]) + b)
__device__ __forceinline__ void fma8(float* acc, uint4 v, float w) {
    float2 f0 = __half22float2(*(__half2*)&v.x);
    float2 f1 = __half22float2(*(__half2*)&v.y);
    float2 f2 = __half22float2(*(__half2*)&v.z);
    float2 f3 = __half22float2(*(__half2*)&v.w);
    acc[0] = fmaf(f0.x, w, acc[0]); acc[1] = fmaf(f0.y, w, acc[1]);
    acc[2] = fmaf(f1.x, w, acc[2]); acc[3] = fmaf(f1.y, w, acc[3]);
    acc[4] = fmaf(f2.x, w, acc[4]); acc[5] = fmaf(f2.y, w, acc[5]);
    acc[6] = fmaf(f3.x, w, acc[6]); acc[7] = fmaf(f3.y, w, acc[7]);
}

template<int C, bool RELU>
__global__ void aggregate_kernel(const __half* __restrict__ h,
                                 const float* __restrict__ bias,
                                 float* __restrict__ out) {
    constexpr int TPN = C / 8;            // lanes per node (uint4 = 8 halves)
    constexpr int NPB = 256 / TPN;        // nodes per block (256-thread blocks)
    int local = threadIdx.x / TPN;
    int c8 = threadIdx.x % TPN;
    int node = blockIdx.x * NPB + local;
    if (node >= N_NODES) return;

    const uint4* h8 = (const uint4*)h;
    const size_t S = C / 8;
    float d = g_dis[node];

    float acc[8] = {};
    fma8(acc, __ldg(&h8[(size_t)node * S + c8]), d);   // self-loop: dis[d]*h[d]

    int beg = g_row_off[node];
    int end = beg + g_indeg[node];
    int p = beg;
    for (; p + 4 <= end; p += 4) {
        int s0 = g_csr_src[p],   s1 = g_csr_src[p+1];
        int s2 = g_csr_src[p+2], s3 = g_csr_src[p+3];
        float w0 = g_csr_w[p],   w1 = g_csr_w[p+1];
        float w2 = g_csr_w[p+2], w3 = g_csr_w[p+3];
        uint4 v0 = __ldg(&h8[(size_t)s0 * S + c8]);
        uint4 v1 = __ldg(&h8[(size_t)s1 * S + c8]);
        uint4 v2 = __ldg(&h8[(size_t)s2 * S + c8]);
        uint4 v3 = __ldg(&h8[(size_t)s3 * S + c8]);
        fma8(acc, v0, w0); fma8(acc, v1, w1); fma8(acc, v2, w2); fma8(acc, v3, w3);
    }
    for (; p < end; ++p)
        fma8(acc, __ldg(&h8[(size_t)g_csr_src[p] * S + c8]), g_csr_w[p]);

    int colb = c8 * 8;
    float4 b0 = __ldg(&((const float4*)bias)[c8 * 2]);
    float4 b1 = __ldg(&((const float4*)bias)[c8 * 2 + 1]);
    float4 r0, r1;
    r0.x = fmaf(d, acc[0], b0.x); r0.y = fmaf(d, acc[1], b0.y);
    r0.z = fmaf(d, acc[2], b0.z); r0.w = fmaf(d, acc[3], b0.w);
    r1.x = fmaf(d, acc[4], b1.x); r1.y = fmaf(d, acc[5], b1.y);
    r1.z = fmaf(d, acc[6], b1.z); r1.w = fmaf(d, acc[7], b1.w);
    if (RELU) {
        r0.x = fmaxf(r0.x, 0.f); r0.y = fmaxf(r0.y, 0.f);
        r0.z = fmaxf(r0.z, 0.f); r0.w = fmaxf(r0.w, 0.f);
        r1.x = fmaxf(r1.x, 0.f); r1.y = fmaxf(r1.y, 0.f);
        r1.z = fmaxf(r1.z, 0.f); r1.w = fmaxf(r1.w, 0.f);
    }
    *(float4*)&out[(size_t)node * C + colb]     = r0;
    *(float4*)&out[(size_t)node * C + colb + 4] = r1;
}

// ---------------- driver ----------------
static inline int cdiv(long long a, long long b) { return (int)((a + b - 1) / b); }

extern "C" void kernel_launch(void* const* d_in, const int* in_sizes, int n_in,
                              void* d_out, int out_size) {
    const float* x  = (const float*)d_in[0];
    const float* W1 = (const float*)d_in[1];
    const float* b1 = (const float*)d_in[2];
    const float* W2 = (const float*)d_in[3];
    const float* b2 = (const float*)d_in[4];
    const float* W3 = (const float*)d_in[5];
    const float* b3 = (const float*)d_in[6];
    const int*   ei = (const int*)d_in[7];   // int32 (JAX default dtype demotion)
    int E = in_sizes[7] / 2;
    float* out = (float*)d_out;

    __half* h;
    float* t;
    cudaGetSymbolAddress((void**)&h, g_h);
    cudaGetSymbolAddress((void**)&t, g_t);

    // infrastructure handles (created on the eager correctness call, not during capture)
    static cudaStream_t s2 = [] {
        cudaStream_t s; cudaStreamCreateWithFlags(&s, cudaStreamNonBlocking); return s;
    }();
    static cudaEvent_t eFork = [] {
        cudaEvent_t e; cudaEventCreateWithFlags(&e, cudaEventDisableTiming); return e;
    }();
    static cudaEvent_t eJoin = [] {
        cudaEvent_t e; cudaEventCreateWithFlags(&e, cudaEventDisableTiming); return e;
    }();

    const int TPB = 256;

    // ---- fork: ENTIRE CSR build on s2, hidden under layer-1 GEMM ----
    cudaEventRecord(eFork, 0);
    cudaStreamWaitEvent(s2, eFork, 0);
    zero_counts_kernel<<<cdiv(N_NODES, TPB), TPB, 0, s2>>>();
    count_kernel<<<cdiv(E, TPB), TPB, 0, s2>>>(ei, E);
    scan_kernel<<<1, 1024, 0, s2>>>();
    fill_kernel<<<cdiv(E, TPB), TPB, 0, s2>>>(ei, E);
    cudaEventRecord(eJoin, s2);

    // ---- layer 1: 256 -> 256, relu ----
    {
        dim3 grid(256 / 64, cdiv(N_NODES, 128));
        gemm_f16_kernel<<<grid, 256>>>(x, W1, h, N_NODES, 256, 256);
        cudaStreamWaitEvent(0, eJoin, 0);
        aggregate_kernel<256, true><<<cdiv(N_NODES, 8), 256>>>(h, b1, t);
    }
    // ---- layer 2: 256 -> 128, relu ----
    {
        dim3 grid(128 / 64, cdiv(N_NODES, 128));
        gemm_f16_kernel<<<grid, 256>>>(t, W2, h, N_NODES, 128, 256);
        aggregate_kernel<128, true><<<cdiv(N_NODES, 16), 256>>>(h, b2, t);
    }
    // ---- layer 3: 128 -> 64, no relu ----
    {
        dim3 grid(64 / 64, cdiv(N_NODES, 128));
        gemm_f16_kernel<<<grid, 256>>>(t, W3, h, N_NODES, 64, 128);
        aggregate_kernel<64, false><<<cdiv(N_NODES, 32), 256>>>(h, b3, out);
    }
}

// round 12
// speedup vs baseline: 1.1320x; 1.0753x over previous
#include <cuda_runtime.h>
#include <cuda_fp16.h>
#include <cstdint>

#define N_NODES 20000
#define MAXC 256
#define SLOT_SHIFT 6               // 64 slots per node (max indeg; Poisson(16) tail ~e^-40)
#define SLOTS (1 << SLOT_SHIFT)

// ---------------- scratch ----------------
__device__ int    g_fill[N_NODES];                     // indeg after fill
__device__ float  g_dis[N_NODES];
__device__ int    g_slots[(size_t)N_NODES * SLOTS];    // src lists, fixed stride
__device__ __half g_h[(size_t)N_NODES * MAXC];         // GEMM output (fp16, unscaled)
__device__ float  g_t[(size_t)N_NODES * MAXC];         // layer activation (fp32)

// ---------------- prep ----------------
__global__ void zero_fill_kernel() {
    int i = blockIdx.x * blockDim.x + threadIdx.x;
    if (i < N_NODES) g_fill[i] = 0;
}

__global__ void fill_kernel(const int* __restrict__ ei, int E) {
    int e = blockIdx.x * blockDim.x + threadIdx.x;
    if (e < E) {
        int s = ei[e];
        int d = ei[E + e];
        int pos = atomicAdd(&g_fill[d], 1);
        g_slots[((size_t)d << SLOT_SHIFT) + pos] = s;
    }
}

__global__ void dis_kernel() {
    int i = blockIdx.x * blockDim.x + threadIdx.x;
    if (i < N_NODES) g_dis[i] = rsqrtf((float)g_fill[i] + 1.0f);   // +1 self-loop
}

// ---------------- FP16 tensor-core GEMM (m16n8k16, fp32 accum, BK=16) ----------------
// Ch[M,N] = half(A[M,K] @ B[K,N]); A,B fp32 in, converted to fp16 tiles.
__global__ void gemm_f16_kernel(const float* __restrict__ A, const float* __restrict__ B,
                                __half* __restrict__ Ch, int M, int N, int K) {
    const int BM = 128, BN = 64, BK = 16;
    __shared__ __half2 As[2][BM][9];    // [m][k/2], stride 9 words
    __shared__ __half  Bs[2][BN][18];   // [n][k], stride 18 halves

    int tid = threadIdx.x;
    int lane = tid & 31;
    int wid = tid >> 5;
    int warp_m = wid & 3;
    int warp_n = wid >> 2;
    int brow = blockIdx.y * BM;
    int bcol = blockIdx.x * BN;

    int g = lane >> 2;
    int tg = lane & 3;

    float acc[2][4][4];
    #pragma unroll
    for (int i = 0; i < 2; i++)
        #pragma unroll
        for (int j = 0; j < 4; j++)
            #pragma unroll
            for (int q = 0; q < 4; q++) acc[i][j][q] = 0.0f;

    __half2 ra[4];
    __half  rbv[4];

    #pragma unroll
    for (int i = 0; i < 4; i++) {
        int lin = tid + i * 256;
        int m = lin >> 3, j = lin & 7;
        int gr = brow + m;
        float2 f = (gr < M) ? *(const float2*)&A[(size_t)gr * K + 2 * j]
                            : make_float2(0.f, 0.f);
        As[0][m][j] = __floats2half2_rn(f.x, f.y);
    }
    #pragma unroll
    for (int i = 0; i < 4; i++) {
        int lin = tid + i * 256;
        int k = lin >> 6, n = lin & 63;
        Bs[0][n][k] = __float2half_rn(B[(size_t)k * N + bcol + n]);
    }
    __syncthreads();

    int KT = K / BK;
    int cur = 0;
    for (int kt = 0; kt < KT; kt++) {
        bool more = (kt + 1 < KT);
        if (more) {
            int k0n = (kt + 1) * BK;
            #pragma unroll
            for (int i = 0; i < 4; i++) {
                int lin = tid + i * 256;
                int m = lin >> 3, j = lin & 7;
                int gr = brow + m;
                float2 f = (gr < M) ? *(const float2*)&A[(size_t)gr * K + k0n + 2 * j]
                                    : make_float2(0.f, 0.f);
                ra[i] = __floats2half2_rn(f.x, f.y);
            }
            #pragma unroll
            for (int i = 0; i < 4; i++) {
                int lin = tid + i * 256;
                int k = lin >> 6, n = lin & 63;
                rbv[i] = __float2half_rn(B[(size_t)(k0n + k) * N + bcol + n]);
            }
        }

        uint32_t af[2][4], bf[4][2];
        #pragma unroll
        for (int mt = 0; mt < 2; mt++) {
            int r0 = warp_m * 32 + mt * 16 + g;
            af[mt][0] = *(const uint32_t*)&As[cur][r0][tg];
            af[mt][1] = *(const uint32_t*)&As[cur][r0 + 8][tg];
            af[mt][2] = *(const uint32_t*)&As[cur][r0][tg + 4];
            af[mt][3] = *(const uint32_t*)&As[cur][r0 + 8][tg + 4];
        }
        #pragma unroll
        for (int nt = 0; nt < 4; nt++) {
            int c0 = warp_n * 32 + nt * 8 + g;
            bf[nt][0] = *(const uint32_t*)&Bs[cur][c0][2 * tg];
            bf[nt][1] = *(const uint32_t*)&Bs[cur][c0][2 * tg + 8];
        }
        #pragma unroll
        for (int mt = 0; mt < 2; mt++)
            #pragma unroll
            for (int nt = 0; nt < 4; nt++) {
                asm volatile(
                    "mma.sync.aligned.m16n8k16.row.col.f32.f16.f16.f32 "
                    "{%0,%1,%2,%3}, {%4,%5,%6,%7}, {%8,%9}, {%0,%1,%2,%3};"
                    : "+f"(acc[mt][nt][0]), "+f"(acc[mt][nt][1]),
                      "+f"(acc[mt][nt][2]), "+f"(acc[mt][nt][3])
                    : "r"(af[mt][0]), "r"(af[mt][1]), "r"(af[mt][2]), "r"(af[mt][3]),
                      "r"(bf[nt][0]), "r"(bf[nt][1]));
            }

        if (more) {
            int nxt = cur ^ 1;
            #pragma unroll
            for (int i = 0; i < 4; i++) {
                int lin = tid + i * 256;
                int m = lin >> 3, j = lin & 7;
                As[nxt][m][j] = ra[i];
            }
            #pragma unroll
            for (int i = 0; i < 4; i++) {
                int lin = tid + i * 256;
                int k = lin >> 6, n = lin & 63;
                Bs[nxt][n][k] = rbv[i];
            }
            __syncthreads();
            cur = nxt;
        }
    }

    #pragma unroll
    for (int mt = 0; mt < 2; mt++) {
        int r0 = brow + warp_m * 32 + mt * 16 + g;
        int r1 = r0 + 8;
        #pragma unroll
        for (int nt = 0; nt < 4; nt++) {
            int cc = bcol + warp_n * 32 + nt * 8 + 2 * tg;
            if (r0 < M) {
                __half2 v = __floats2half2_rn(acc[mt][nt][0], acc[mt][nt][1]);
                *(__half2*)&Ch[(size_t)r0 * N + cc] = v;
            }
            if (r1 < M) {
                __half2 v = __floats2half2_rn(acc[mt][nt][2], acc[mt][nt][3]);
                *(__half2*)&Ch[(size_t)r1 * N + cc] = v;
            }
        }
    }
}

// ---------------- fused aggregate + self-loop + bias (+relu) ----------------
// h unscaled fp16; out[d] = relu(dis[d]*(sum_s dis[s]*h[s] + dis[d]*h[d]) + b)
__device__ __forceinline__ void fma8(float* acc, uint4 v, float w) {
    float2 f0 = __half22float2(*(__half2*)&v.x);
    float2 f1 = __half22float2(*(__half2*)&v.y);
    float2 f2 = __half22float2(*(__half2*)&v.z);
    float2 f3 = __half22float2(*(__half2*)&v.w);
    acc[0] = fmaf(f0.x, w, acc[0]); acc[1] = fmaf(f0.y, w, acc[1]);
    acc[2] = fmaf(f1.x, w, acc[2]); acc[3] = fmaf(f1.y, w, acc[3]);
    acc[4] = fmaf(f2.x, w, acc[4]); acc[5] = fmaf(f2.y, w, acc[5]);
    acc[6] = fmaf(f3.x, w, acc[6]); acc[7] = fmaf(f3.y, w, acc[7]);
}

template<int C, bool RELU>
__global__ void aggregate_kernel(const __half* __restrict__ h,
                                 const float* __restrict__ bias,
                                 float* __restrict__ out) {
    constexpr int TPN = C / 8;            // lanes per node (uint4 = 8 halves)
    constexpr int NPB = 128 / TPN;        // nodes per block
    int local = threadIdx.x / TPN;
    int c8 = threadIdx.x % TPN;
    int node = blockIdx.x * NPB + local;
    if (node >= N_NODES) return;

    const uint4* h8 = (const uint4*)h;
    const size_t S = C / 8;
    int indeg = __ldg(&g_fill[node]);
    float d = rsqrtf((float)indeg + 1.0f);

    float acc[8] = {};
    fma8(acc, __ldg(&h8[(size_t)node * S + c8]), d);   // self-loop: dis[d]*h[d]

    const int* slots = &g_slots[(size_t)node << SLOT_SHIFT];
    int p = 0;
    for (; p + 4 <= indeg; p += 4) {
        int s0 = __ldg(&slots[p]),     s1 = __ldg(&slots[p + 1]);
        int s2 = __ldg(&slots[p + 2]), s3 = __ldg(&slots[p + 3]);
        float w0 = __ldg(&g_dis[s0]),  w1 = __ldg(&g_dis[s1]);
        float w2 = __ldg(&g_dis[s2]),  w3 = __ldg(&g_dis[s3]);
        uint4 v0 = __ldg(&h8[(size_t)s0 * S + c8]);
        uint4 v1 = __ldg(&h8[(size_t)s1 * S + c8]);
        uint4 v2 = __ldg(&h8[(size_t)s2 * S + c8]);
        uint4 v3 = __ldg(&h8[(size_t)s3 * S + c8]);
        fma8(acc, v0, w0); fma8(acc, v1, w1); fma8(acc, v2, w2); fma8(acc, v3, w3);
    }
    for (; p < indeg; ++p) {
        int s = __ldg(&slots[p]);
        fma8(acc, __ldg(&h8[(size_t)s * S + c8]), __ldg(&g_dis[s]));
    }

    int colb = c8 * 8;
    float4 b0 = __ldg(&((const float4*)bias)[c8 * 2]);
    float4 b1 = __ldg(&((const float4*)bias)[c8 * 2 + 1]);
    float4 r0, r1;
    r0.x = fmaf(d, acc[0], b0.x); r0.y = fmaf(d, acc[1], b0.y);
    r0.z = fmaf(d, acc[2], b0.z); r0.w = fmaf(d, acc[3], b0.w);
    r1.x = fmaf(d, acc[4], b1.x); r1.y = fmaf(d, acc[5], b1.y);
    r1.z = fmaf(d, acc[6], b1.z); r1.w = fmaf(d, acc[7], b1.w);
    if (RELU) {
        r0.x = fmaxf(r0.x, 0.f); r0.y = fmaxf(r0.y, 0.f);
        r0.z = fmaxf(r0.z, 0.f); r0.w = fmaxf(r0.w, 0.f);
        r1.x = fmaxf(r1.x, 0.f); r1.y = fmaxf(r1.y, 0.f);
        r1.z = fmaxf(r1.z, 0.f); r1.w = fmaxf(r1.w, 0.f);
    }
    *(float4*)&out[(size_t)node * C + colb]     = r0;
    *(float4*)&out[(size_t)node * C + colb + 4] = r1;
}

// ---------------- driver ----------------
static inline int cdiv(long long a, long long b) { return (int)((a + b - 1) / b); }

extern "C" void kernel_launch(void* const* d_in, const int* in_sizes, int n_in,
                              void* d_out, int out_size) {
    const float* x  = (const float*)d_in[0];
    const float* W1 = (const float*)d_in[1];
    const float* b1 = (const float*)d_in[2];
    const float* W2 = (const float*)d_in[3];
    const float* b2 = (const float*)d_in[4];
    const float* W3 = (const float*)d_in[5];
    const float* b3 = (const float*)d_in[6];
    const int*   ei = (const int*)d_in[7];   // int32 (JAX default dtype demotion)
    int E = in_sizes[7] / 2;
    float* out = (float*)d_out;

    __half* h;
    float* t;
    cudaGetSymbolAddress((void**)&h, g_h);
    cudaGetSymbolAddress((void**)&t, g_t);

    // infrastructure handles (created on the eager correctness call, not during capture)
    static cudaStream_t s2 = [] {
        cudaStream_t s; cudaStreamCreateWithFlags(&s, cudaStreamNonBlocking); return s;
    }();
    static cudaEvent_t eFork = [] {
        cudaEvent_t e; cudaEventCreateWithFlags(&e, cudaEventDisableTiming); return e;
    }();
    static cudaEvent_t eJoin = [] {
        cudaEvent_t e; cudaEventCreateWithFlags(&e, cudaEventDisableTiming); return e;
    }();

    const int TPB = 256;

    // ---- fork: slot build on s2, hidden under layer-1 GEMM ----
    cudaEventRecord(eFork, 0);
    cudaStreamWaitEvent(s2, eFork, 0);
    zero_fill_kernel<<<cdiv(N_NODES, TPB), TPB, 0, s2>>>();
    fill_kernel<<<cdiv(E, TPB), TPB, 0, s2>>>(ei, E);
    dis_kernel<<<cdiv(N_NODES, TPB), TPB, 0, s2>>>();
    cudaEventRecord(eJoin, s2);

    // ---- layer 1: 256 -> 256, relu ----
    {
        dim3 grid(256 / 64, cdiv(N_NODES, 128));
        gemm_f16_kernel<<<grid, 256>>>(x, W1, h, N_NODES, 256, 256);
        cudaStreamWaitEvent(0, eJoin, 0);
        aggregate_kernel<256, true><<<cdiv(N_NODES, 4), 128>>>(h, b1, t);
    }
    // ---- layer 2: 256 -> 128, relu ----
    {
        dim3 grid(128 / 64, cdiv(N_NODES, 128));
        gemm_f16_kernel<<<grid, 256>>>(t, W2, h, N_NODES, 128, 256);
        aggregate_kernel<128, true><<<cdiv(N_NODES, 8), 128>>>(h, b2, t);
    }
    // ---- layer 3: 128 -> 64, no relu ----
    {
        dim3 grid(64 / 64, cdiv(N_NODES, 128));
        gemm_f16_kernel<<<grid, 256>>>(t, W3, h, N_NODES, 64, 128);
        aggregate_kernel<64, false><<<cdiv(N_NODES, 16), 128>>>(h, b3, out);
    }
}

// round 13
// speedup vs baseline: 1.2573x; 1.1106x over previous
#include <cuda_runtime.h>
#include <cuda_fp16.h>
#include <cstdint>

#define N_NODES 20000
#define MAXC 256
#define SLOT_SHIFT 6               // 64 slots per node (max indeg; Poisson(16) tail ~e^-40)
#define SLOTS (1 << SLOT_SHIFT)

// ---------------- scratch ----------------
__device__ int    g_fill[N_NODES];                     // indeg after fill
__device__ float  g_dis[N_NODES];
__device__ int    g_slots[(size_t)N_NODES * SLOTS];    // src lists, fixed stride
__device__ __half g_h[(size_t)N_NODES * MAXC];         // GEMM output (fp16, unscaled)
__device__ float  g_t[(size_t)N_NODES * MAXC];         // layer activation (fp32)

// ---------------- prep ----------------
__global__ void zero_fill_kernel() {
    int i = blockIdx.x * blockDim.x + threadIdx.x;
    if (i < N_NODES) g_fill[i] = 0;
}

__global__ void fill_kernel(const int* __restrict__ ei, int E) {
    int e = blockIdx.x * blockDim.x + threadIdx.x;
    if (e < E) {
        int s = ei[e];
        int d = ei[E + e];
        int pos = atomicAdd(&g_fill[d], 1);
        g_slots[((size_t)d << SLOT_SHIFT) + pos] = s;
    }
}

__global__ void dis_kernel() {
    int i = blockIdx.x * blockDim.x + threadIdx.x;
    if (i < N_NODES) g_dis[i] = rsqrtf((float)g_fill[i] + 1.0f);   // +1 self-loop
}

// ---------------- FP16 tensor-core GEMM (m16n8k16, fp32 accum, ldmatrix) ----------------
__device__ __forceinline__ uint32_t smem_u32(const void* p) {
    return (uint32_t)__cvta_generic_to_shared(p);
}

#define LDSM_X4(r0, r1, r2, r3, addr)                                        \
    asm volatile("ldmatrix.sync.aligned.m8n8.x4.shared.b16 {%0,%1,%2,%3}, [%4];" \
                 : "=r"(r0), "=r"(r1), "=r"(r2), "=r"(r3) : "r"(addr))

#define LDSM_X4_T(r0, r1, r2, r3, addr)                                      \
    asm volatile("ldmatrix.sync.aligned.m8n8.x4.trans.shared.b16 {%0,%1,%2,%3}, [%4];" \
                 : "=r"(r0), "=r"(r1), "=r"(r2), "=r"(r3) : "r"(addr))

__global__ void gemm_f16_kernel(const float* __restrict__ A, const float* __restrict__ B,
                                __half* __restrict__ Ch, int M, int N, int K) {
    const int BM = 128, BN = 64, BK = 16;
    const int ASTRIDE = 24;   // halves per A row (48B, 16 used) -> conflict-free ldmatrix
    const int BSTRIDE = 72;   // halves per B k-row (144B, 64 used) -> conflict-free ldmatrix.trans
    __shared__ __half As[2][BM][ASTRIDE];   // [m][k] row-major
    __shared__ __half Bs[2][BK][BSTRIDE];   // [k][n] k-major (as in global)

    const int ABUF = BM * ASTRIDE * 2;      // bytes per A buffer
    const int BBUF = BK * BSTRIDE * 2;

    int tid = threadIdx.x;
    int lane = tid & 31;
    int wid = tid >> 5;
    int warp_m = wid & 3;     // 0..3 -> 32-row slab
    int warp_n = wid >> 2;    // 0..1 -> 32-col slab
    int brow = blockIdx.y * BM;
    int bcol = blockIdx.x * BN;

    float acc[2][4][4];
    #pragma unroll
    for (int i = 0; i < 2; i++)
        #pragma unroll
        for (int j = 0; j < 4; j++)
            #pragma unroll
            for (int q = 0; q < 4; q++) acc[i][j][q] = 0.0f;

    // ldmatrix lane addresses (byte offsets within a buffer)
    int l15 = lane & 15;
    int lhi = lane >> 4;      // 0,1
    uint32_t sA = smem_u32(&As[0][0][0]);
    uint32_t sB = smem_u32(&Bs[0][0][0]);
    uint32_t aoff[2], boff[2];
    #pragma unroll
    for (int mt = 0; mt < 2; mt++)
        aoff[mt] = sA + (uint32_t)(((warp_m * 32 + mt * 16 + l15) * ASTRIDE + lhi * 8) * 2);
    #pragma unroll
    for (int p = 0; p < 2; p++)
        boff[p] = sB + (uint32_t)((l15 * BSTRIDE + warp_n * 32 + p * 16 + lhi * 8) * 2);

    __half2 ra[4];
    __half2 rb2[2];

    // ---- prologue: tile 0 ----
    #pragma unroll
    for (int i = 0; i < 4; i++) {            // A: 128 rows x 8 half2
        int lin = tid + i * 256;
        int m = lin >> 3, j = lin & 7;
        int gr = brow + m;
        float2 f = (gr < M) ? *(const float2*)&A[(size_t)gr * K + 2 * j]
                            : make_float2(0.f, 0.f);
        *(__half2*)&As[0][m][2 * j] = __floats2half2_rn(f.x, f.y);
    }
    #pragma unroll
    for (int i = 0; i < 2; i++) {            // B: 16 k-rows x 32 half2
        int lin = tid + i * 256;
        int k = lin >> 5, n2 = lin & 31;
        float2 f = *(const float2*)&B[(size_t)k * N + bcol + 2 * n2];
        *(__half2*)&Bs[0][k][2 * n2] = __floats2half2_rn(f.x, f.y);
    }
    __syncthreads();

    int KT = K / BK;
    int cur = 0;
    for (int kt = 0; kt < KT; kt++) {
        bool more = (kt + 1 < KT);
        if (more) {
            int k0n = (kt + 1) * BK;
            #pragma unroll
            for (int i = 0; i < 4; i++) {
                int lin = tid + i * 256;
                int m = lin >> 3, j = lin & 7;
                int gr = brow + m;
                float2 f = (gr < M) ? *(const float2*)&A[(size_t)gr * K + k0n + 2 * j]
                                    : make_float2(0.f, 0.f);
                ra[i] = __floats2half2_rn(f.x, f.y);
            }
            #pragma unroll
            for (int i = 0; i < 2; i++) {
                int lin = tid + i * 256;
                int k = lin >> 5, n2 = lin & 31;
                float2 f = *(const float2*)&B[(size_t)(k0n + k) * N + bcol + 2 * n2];
                rb2[i] = __floats2half2_rn(f.x, f.y);
            }
        }

        // fragment loads via ldmatrix
        uint32_t a[2][4], b[2][4];
        uint32_t bufA = cur * ABUF, bufB = cur * BBUF;
        #pragma unroll
        for (int mt = 0; mt < 2; mt++)
            LDSM_X4(a[mt][0], a[mt][1], a[mt][2], a[mt][3], aoff[mt] + bufA);
        #pragma unroll
        for (int p = 0; p < 2; p++)
            LDSM_X4_T(b[p][0], b[p][1], b[p][2], b[p][3], boff[p] + bufB);

        #pragma unroll
        for (int mt = 0; mt < 2; mt++)
            #pragma unroll
            for (int nt = 0; nt < 4; nt++) {
                uint32_t b0 = b[nt >> 1][(nt & 1) * 2];
                uint32_t b1 = b[nt >> 1][(nt & 1) * 2 + 1];
                asm volatile(
                    "mma.sync.aligned.m16n8k16.row.col.f32.f16.f16.f32 "
                    "{%0,%1,%2,%3}, {%4,%5,%6,%7}, {%8,%9}, {%0,%1,%2,%3};"
                    : "+f"(acc[mt][nt][0]), "+f"(acc[mt][nt][1]),
                      "+f"(acc[mt][nt][2]), "+f"(acc[mt][nt][3])
                    : "r"(a[mt][0]), "r"(a[mt][1]), "r"(a[mt][2]), "r"(a[mt][3]),
                      "r"(b0), "r"(b1));
            }

        if (more) {
            int nxt = cur ^ 1;
            __syncthreads();   // fragment reads done before overwrite? (double buffer: writes go to nxt, no hazard) — kept minimal below
            #pragma unroll
            for (int i = 0; i < 4; i++) {
                int lin = tid + i * 256;
                int m = lin >> 3, j = lin & 7;
                *(__half2*)&As[nxt][m][2 * j] = ra[i];
            }
            #pragma unroll
            for (int i = 0; i < 2; i++) {
                int lin = tid + i * 256;
                int k = lin >> 5, n2 = lin & 31;
                *(__half2*)&Bs[nxt][k][2 * n2] = rb2[i];
            }
            __syncthreads();
            cur = nxt;
        }
    }

    // epilogue: fp16 store, (c0,c1)/(c2,c3) as half2
    int g = lane >> 2;
    int tg = lane & 3;
    #pragma unroll
    for (int mt = 0; mt < 2; mt++) {
        int r0 = brow + warp_m * 32 + mt * 16 + g;
        int r1 = r0 + 8;
        #pragma unroll
        for (int nt = 0; nt < 4; nt++) {
            int cc = bcol + warp_n * 32 + nt * 8 + 2 * tg;
            if (r0 < M) {
                __half2 v = __floats2half2_rn(acc[mt][nt][0], acc[mt][nt][1]);
                *(__half2*)&Ch[(size_t)r0 * N + cc] = v;
            }
            if (r1 < M) {
                __half2 v = __floats2half2_rn(acc[mt][nt][2], acc[mt][nt][3]);
                *(__half2*)&Ch[(size_t)r1 * N + cc] = v;
            }
        }
    }
}

// ---------------- fused aggregate + self-loop + bias (+relu) ----------------
__device__ __forceinline__ void fma8(float* acc, uint4 v, float w) {
    float2 f0 = __half22float2(*(__half2*)&v.x);
    float2 f1 = __half22float2(*(__half2*)&v.y);
    float2 f2 = __half22float2(*(__half2*)&v.z);
    float2 f3 = __half22float2(*(__half2*)&v.w);
    acc[0] = fmaf(f0.x, w, acc[0]); acc[1] = fmaf(f0.y, w, acc[1]);
    acc[2] = fmaf(f1.x, w, acc[2]); acc[3] = fmaf(f1.y, w, acc[3]);
    acc[4] = fmaf(f2.x, w, acc[4]); acc[5] = fmaf(f2.y, w, acc[5]);
    acc[6] = fmaf(f3.x, w, acc[6]); acc[7] = fmaf(f3.y, w, acc[7]);
}

template<int C, bool RELU>
__global__ void aggregate_kernel(const __half* __restrict__ h,
                                 const float* __restrict__ bias,
                                 float* __restrict__ out) {
    constexpr int TPN = C / 8;            // lanes per node (uint4 = 8 halves)
    constexpr int NPB = 128 / TPN;        // nodes per block
    int local = threadIdx.x / TPN;
    int c8 = threadIdx.x % TPN;
    int node = blockIdx.x * NPB + local;
    if (node >= N_NODES) return;

    const uint4* h8 = (const uint4*)h;
    const size_t S = C / 8;
    int indeg = __ldg(&g_fill[node]);
    float d = rsqrtf((float)indeg + 1.0f);

    float acc[8] = {};
    fma8(acc, __ldg(&h8[(size_t)node * S + c8]), d);   // self-loop: dis[d]*h[d]

    const int* slots = &g_slots[(size_t)node << SLOT_SHIFT];
    int p = 0;
    for (; p + 4 <= indeg; p += 4) {
        int s0 = __ldg(&slots[p]),     s1 = __ldg(&slots[p + 1]);
        int s2 = __ldg(&slots[p + 2]), s3 = __ldg(&slots[p + 3]);
        float w0 = __ldg(&g_dis[s0]),  w1 = __ldg(&g_dis[s1]);
        float w2 = __ldg(&g_dis[s2]),  w3 = __ldg(&g_dis[s3]);
        uint4 v0 = __ldg(&h8[(size_t)s0 * S + c8]);
        uint4 v1 = __ldg(&h8[(size_t)s1 * S + c8]);
        uint4 v2 = __ldg(&h8[(size_t)s2 * S + c8]);
        uint4 v3 = __ldg(&h8[(size_t)s3 * S + c8]);
        fma8(acc, v0, w0); fma8(acc, v1, w1); fma8(acc, v2, w2); fma8(acc, v3, w3);
    }
    for (; p < indeg; ++p) {
        int s = __ldg(&slots[p]);
        fma8(acc, __ldg(&h8[(size_t)s * S + c8]), __ldg(&g_dis[s]));
    }

    int colb = c8 * 8;
    float4 b0 = __ldg(&((const float4*)bias)[c8 * 2]);
    float4 b1 = __ldg(&((const float4*)bias)[c8 * 2 + 1]);
    float4 r0, r1;
    r0.x = fmaf(d, acc[0], b0.x); r0.y = fmaf(d, acc[1], b0.y);
    r0.z = fmaf(d, acc[2], b0.z); r0.w = fmaf(d, acc[3], b0.w);
    r1.x = fmaf(d, acc[4], b1.x); r1.y = fmaf(d, acc[5], b1.y);
    r1.z = fmaf(d, acc[6], b1.z); r1.w = fmaf(d, acc[7], b1.w);
    if (RELU) {
        r0.x = fmaxf(r0.x, 0.f); r0.y = fmaxf(r0.y, 0.f);
        r0.z = fmaxf(r0.z, 0.f); r0.w = fmaxf(r0.w, 0.f);
        r1.x = fmaxf(r1.x, 0.f); r1.y = fmaxf(r1.y, 0.f);
        r1.z = fmaxf(r1.z, 0.f); r1.w = fmaxf(r1.w, 0.f);
    }
    *(float4*)&out[(size_t)node * C + colb]     = r0;
    *(float4*)&out[(size_t)node * C + colb + 4] = r1;
}

// ---------------- driver ----------------
static inline int cdiv(long long a, long long b) { return (int)((a + b - 1) / b); }

extern "C" void kernel_launch(void* const* d_in, const int* in_sizes, int n_in,
                              void* d_out, int out_size) {
    const float* x  = (const float*)d_in[0];
    const float* W1 = (const float*)d_in[1];
    const float* b1 = (const float*)d_in[2];
    const float* W2 = (const float*)d_in[3];
    const float* b2 = (const float*)d_in[4];
    const float* W3 = (const float*)d_in[5];
    const float* b3 = (const float*)d_in[6];
    const int*   ei = (const int*)d_in[7];   // int32 (JAX default dtype demotion)
    int E = in_sizes[7] / 2;
    float* out = (float*)d_out;

    __half* h;
    float* t;
    cudaGetSymbolAddress((void**)&h, g_h);
    cudaGetSymbolAddress((void**)&t, g_t);

    // infrastructure handles (created on the eager correctness call, not during capture)
    static cudaStream_t s2 = [] {
        cudaStream_t s; cudaStreamCreateWithFlags(&s, cudaStreamNonBlocking); return s;
    }();
    static cudaEvent_t eFork = [] {
        cudaEvent_t e; cudaEventCreateWithFlags(&e, cudaEventDisableTiming); return e;
    }();
    static cudaEvent_t eJoin = [] {
        cudaEvent_t e; cudaEventCreateWithFlags(&e, cudaEventDisableTiming); return e;
    }();

    const int TPB = 256;

    // ---- fork: slot build on s2, hidden under layer-1 GEMM ----
    cudaEventRecord(eFork, 0);
    cudaStreamWaitEvent(s2, eFork, 0);
    zero_fill_kernel<<<cdiv(N_NODES, TPB), TPB, 0, s2>>>();
    fill_kernel<<<cdiv(E, TPB), TPB, 0, s2>>>(ei, E);
    dis_kernel<<<cdiv(N_NODES, TPB), TPB, 0, s2>>>();
    cudaEventRecord(eJoin, s2);

    // ---- layer 1: 256 -> 256, relu ----
    {
        dim3 grid(256 / 64, cdiv(N_NODES, 128));
        gemm_f16_kernel<<<grid, 256>>>(x, W1, h, N_NODES, 256, 256);
        cudaStreamWaitEvent(0, eJoin, 0);
        aggregate_kernel<256, true><<<cdiv(N_NODES, 4), 128>>>(h, b1, t);
    }
    // ---- layer 2: 256 -> 128, relu ----
    {
        dim3 grid(128 / 64, cdiv(N_NODES, 128));
        gemm_f16_kernel<<<grid, 256>>>(t, W2, h, N_NODES, 128, 256);
        aggregate_kernel<128, true><<<cdiv(N_NODES, 8), 128>>>(h, b2, t);
    }
    // ---- layer 3: 128 -> 64, no relu ----
    {
        dim3 grid(64 / 64, cdiv(N_NODES, 128));
        gemm_f16_kernel<<<grid, 256>>>(t, W3, h, N_NODES, 64, 128);
        aggregate_kernel<64, false><<<cdiv(N_NODES, 16), 128>>>(h, b3, out);
    }
}

// round 14
// speedup vs baseline: 1.4436x; 1.1482x over previous
#include <cuda_runtime.h>
#include <cuda_fp16.h>
#include <cstdint>
#include <type_traits>

#define N_NODES 20000
#define MAXC 256
#define SLOT_SHIFT 6               // 64 slots per node (max indeg; Poisson(16) tail ~e^-40)
#define SLOTS (1 << SLOT_SHIFT)

// ---------------- scratch ----------------
__device__ int    g_fill[N_NODES];                     // indeg after fill
__device__ float  g_dis[N_NODES];
__device__ int    g_slots[(size_t)N_NODES * SLOTS];    // src lists, fixed stride
__device__ __half g_h[(size_t)N_NODES * MAXC];         // GEMM output (fp16)
__device__ __half g_t[(size_t)N_NODES * MAXC];         // layer activation (fp16)
__device__ __half g_xh[(size_t)N_NODES * MAXC];        // x converted to fp16
__device__ __half g_w1h[256 * 256];
__device__ __half g_w2h[256 * 128];
__device__ __half g_w3h[128 * 64];

// ---------------- prep ----------------
__global__ void zero_fill_kernel() {
    int i = blockIdx.x * blockDim.x + threadIdx.x;
    if (i < N_NODES) g_fill[i] = 0;
}

__global__ void fill_kernel(const int* __restrict__ ei, int E) {
    int e = blockIdx.x * blockDim.x + threadIdx.x;
    if (e < E) {
        int s = ei[e];
        int d = ei[E + e];
        int pos = atomicAdd(&g_fill[d], 1);
        g_slots[((size_t)d << SLOT_SHIFT) + pos] = s;
    }
}

__global__ void dis_kernel() {
    int i = blockIdx.x * blockDim.x + threadIdx.x;
    if (i < N_NODES) g_dis[i] = rsqrtf((float)g_fill[i] + 1.0f);   // +1 self-loop
}

// fp32 -> fp16, float4 granularity
__global__ void cvt_kernel(const float* __restrict__ in, __half* __restrict__ out, int n4) {
    int i = blockIdx.x * blockDim.x + threadIdx.x;
    if (i < n4) {
        float4 f = ((const float4*)in)[i];
        __half2 h0 = __floats2half2_rn(f.x, f.y);
        __half2 h1 = __floats2half2_rn(f.z, f.w);
        ((__half2*)out)[2 * i]     = h0;
        ((__half2*)out)[2 * i + 1] = h1;
    }
}

// ---------------- FP16 GEMM: cp.async + ldmatrix + m16n8k16 ----------------
__device__ __forceinline__ uint32_t smem_u32(const void* p) {
    return (uint32_t)__cvta_generic_to_shared(p);
}

#define LDSM_X4(r0, r1, r2, r3, addr)                                        \
    asm volatile("ldmatrix.sync.aligned.m8n8.x4.shared.b16 {%0,%1,%2,%3}, [%4];" \
                 : "=r"(r0), "=r"(r1), "=r"(r2), "=r"(r3) : "r"(addr))

#define LDSM_X4_T(r0, r1, r2, r3, addr)                                      \
    asm volatile("ldmatrix.sync.aligned.m8n8.x4.trans.shared.b16 {%0,%1,%2,%3}, [%4];" \
                 : "=r"(r0), "=r"(r1), "=r"(r2), "=r"(r3) : "r"(addr))

__global__ void gemm_f16_kernel(const __half* __restrict__ A, const __half* __restrict__ B,
                                __half* __restrict__ Ch, int M, int N, int K) {
    const int BM = 128, BN = 64, BK = 16;
    const int ASTRIDE = 24;   // halves per A row (48B) -> conflict-free ldmatrix
    const int BSTRIDE = 72;   // halves per B k-row (144B) -> conflict-free ldmatrix.trans
    __shared__ __half As[2][BM][ASTRIDE];
    __shared__ __half Bs[2][BK][BSTRIDE];
    const int ABUF = BM * ASTRIDE * 2;   // bytes per stage
    const int BBUF = BK * BSTRIDE * 2;

    int tid = threadIdx.x;
    int lane = tid & 31;
    int wid = tid >> 5;
    int warp_m = wid & 3;
    int warp_n = wid >> 2;
    int brow = blockIdx.y * BM;
    int bcol = blockIdx.x * BN;

    // cp.async source/dest mapping
    int am = tid >> 1, aj = tid & 1;                // A: 16B per thread
    int bk = tid >> 4, bc = tid & 15;               // B: 8B per thread
    int agr = brow + am;
    const __half* aSrcBase = A + (size_t)agr * K + aj * 8;
    const __half* bSrcBase = B + (size_t)bk * N + bcol + bc * 4;
    uint32_t aDst = smem_u32(&As[0][0][0]) + am * 48 + aj * 16;
    uint32_t bDst = smem_u32(&Bs[0][0][0]) + bk * 144 + bc * 8;
    int aValid = (agr < M) ? 16 : 0;

    float acc[2][4][4];
    #pragma unroll
    for (int i = 0; i < 2; i++)
        #pragma unroll
        for (int j = 0; j < 4; j++)
            #pragma unroll
            for (int q = 0; q < 4; q++) acc[i][j][q] = 0.0f;

    // ldmatrix lane addresses
    int l15 = lane & 15;
    int lhi = lane >> 4;
    uint32_t sA = smem_u32(&As[0][0][0]);
    uint32_t sB = smem_u32(&Bs[0][0][0]);
    uint32_t aoff[2], boff[2];
    #pragma unroll
    for (int mt = 0; mt < 2; mt++)
        aoff[mt] = sA + (uint32_t)(((warp_m * 32 + mt * 16 + l15) * ASTRIDE + lhi * 8) * 2);
    #pragma unroll
    for (int p = 0; p < 2; p++)
        boff[p] = sB + (uint32_t)((l15 * BSTRIDE + warp_n * 32 + p * 16 + lhi * 8) * 2);

    // issue tile kt into buffer kt%2
    auto issue = [&](int kt) {
        int k0 = kt * BK;
        uint32_t ad = aDst + (kt & 1) * ABUF;
        uint32_t bd = bDst + (kt & 1) * BBUF;
        asm volatile("cp.async.cg.shared.global [%0], [%1], 16, %2;"
                     :: "r"(ad), "l"(aSrcBase + k0), "r"(aValid));
        asm volatile("cp.async.ca.shared.global [%0], [%1], 8;"
                     :: "r"(bd), "l"(bSrcBase + (size_t)k0 * N));
        asm volatile("cp.async.commit_group;");
    };

    issue(0);

    int KT = K / BK;
    int cur = 0;
    for (int kt = 0; kt < KT; kt++) {
        bool more = (kt + 1 < KT);
        if (more) issue(kt + 1);
        if (more) asm volatile("cp.async.wait_group 1;");
        else      asm volatile("cp.async.wait_group 0;");
        __syncthreads();

        uint32_t a[2][4], b[2][4];
        uint32_t bufA = cur * ABUF, bufB = cur * BBUF;
        #pragma unroll
        for (int mt = 0; mt < 2; mt++)
            LDSM_X4(a[mt][0], a[mt][1], a[mt][2], a[mt][3], aoff[mt] + bufA);
        #pragma unroll
        for (int p = 0; p < 2; p++)
            LDSM_X4_T(b[p][0], b[p][1], b[p][2], b[p][3], boff[p] + bufB);

        #pragma unroll
        for (int mt = 0; mt < 2; mt++)
            #pragma unroll
            for (int nt = 0; nt < 4; nt++) {
                uint32_t b0 = b[nt >> 1][(nt & 1) * 2];
                uint32_t b1 = b[nt >> 1][(nt & 1) * 2 + 1];
                asm volatile(
                    "mma.sync.aligned.m16n8k16.row.col.f32.f16.f16.f32 "
                    "{%0,%1,%2,%3}, {%4,%5,%6,%7}, {%8,%9}, {%0,%1,%2,%3};"
                    : "+f"(acc[mt][nt][0]), "+f"(acc[mt][nt][1]),
                      "+f"(acc[mt][nt][2]), "+f"(acc[mt][nt][3])
                    : "r"(a[mt][0]), "r"(a[mt][1]), "r"(a[mt][2]), "r"(a[mt][3]),
                      "r"(b0), "r"(b1));
            }

        if (more) __syncthreads();   // protect buf (kt+1)%2 issue next iter
        cur ^= 1;
    }

    // epilogue: fp16 store
    int g = lane >> 2;
    int tg = lane & 3;
    #pragma unroll
    for (int mt = 0; mt < 2; mt++) {
        int r0 = brow + warp_m * 32 + mt * 16 + g;
        int r1 = r0 + 8;
        #pragma unroll
        for (int nt = 0; nt < 4; nt++) {
            int cc = bcol + warp_n * 32 + nt * 8 + 2 * tg;
            if (r0 < M) {
                __half2 v = __floats2half2_rn(acc[mt][nt][0], acc[mt][nt][1]);
                *(__half2*)&Ch[(size_t)r0 * N + cc] = v;
            }
            if (r1 < M) {
                __half2 v = __floats2half2_rn(acc[mt][nt][2], acc[mt][nt][3]);
                *(__half2*)&Ch[(size_t)r1 * N + cc] = v;
            }
        }
    }
}

// ---------------- fused aggregate + self-loop + bias (+relu) ----------------
__device__ __forceinline__ void fma8(float* acc, uint4 v, float w) {
    float2 f0 = __half22float2(*(__half2*)&v.x);
    float2 f1 = __half22float2(*(__half2*)&v.y);
    float2 f2 = __half22float2(*(__half2*)&v.z);
    float2 f3 = __half22float2(*(__half2*)&v.w);
    acc[0] = fmaf(f0.x, w, acc[0]); acc[1] = fmaf(f0.y, w, acc[1]);
    acc[2] = fmaf(f1.x, w, acc[2]); acc[3] = fmaf(f1.y, w, acc[3]);
    acc[4] = fmaf(f2.x, w, acc[4]); acc[5] = fmaf(f2.y, w, acc[5]);
    acc[6] = fmaf(f3.x, w, acc[6]); acc[7] = fmaf(f3.y, w, acc[7]);
}

template<int C, bool RELU, typename OUTT>
__global__ void aggregate_kernel(const __half* __restrict__ h,
                                 const float* __restrict__ bias,
                                 OUTT* __restrict__ out) {
    constexpr int TPN = C / 8;
    constexpr int NPB = 128 / TPN;
    int local = threadIdx.x / TPN;
    int c8 = threadIdx.x % TPN;
    int node = blockIdx.x * NPB + local;
    if (node >= N_NODES) return;

    const uint4* h8 = (const uint4*)h;
    const size_t S = C / 8;
    int indeg = __ldg(&g_fill[node]);
    float d = rsqrtf((float)indeg + 1.0f);

    float acc[8] = {};
    fma8(acc, __ldg(&h8[(size_t)node * S + c8]), d);   // self-loop

    const int* slots = &g_slots[(size_t)node << SLOT_SHIFT];
    int p = 0;
    for (; p + 4 <= indeg; p += 4) {
        int s0 = __ldg(&slots[p]),     s1 = __ldg(&slots[p + 1]);
        int s2 = __ldg(&slots[p + 2]), s3 = __ldg(&slots[p + 3]);
        float w0 = __ldg(&g_dis[s0]),  w1 = __ldg(&g_dis[s1]);
        float w2 = __ldg(&g_dis[s2]),  w3 = __ldg(&g_dis[s3]);
        uint4 v0 = __ldg(&h8[(size_t)s0 * S + c8]);
        uint4 v1 = __ldg(&h8[(size_t)s1 * S + c8]);
        uint4 v2 = __ldg(&h8[(size_t)s2 * S + c8]);
        uint4 v3 = __ldg(&h8[(size_t)s3 * S + c8]);
        fma8(acc, v0, w0); fma8(acc, v1, w1); fma8(acc, v2, w2); fma8(acc, v3, w3);
    }
    for (; p < indeg; ++p) {
        int s = __ldg(&slots[p]);
        fma8(acc, __ldg(&h8[(size_t)s * S + c8]), __ldg(&g_dis[s]));
    }

    int colb = c8 * 8;
    float4 b0 = __ldg(&((const float4*)bias)[c8 * 2]);
    float4 b1 = __ldg(&((const float4*)bias)[c8 * 2 + 1]);
    float r[8];
    r[0] = fmaf(d, acc[0], b0.x); r[1] = fmaf(d, acc[1], b0.y);
    r[2] = fmaf(d, acc[2], b0.z); r[3] = fmaf(d, acc[3], b0.w);
    r[4] = fmaf(d, acc[4], b1.x); r[5] = fmaf(d, acc[5], b1.y);
    r[6] = fmaf(d, acc[6], b1.z); r[7] = fmaf(d, acc[7], b1.w);
    if (RELU) {
        #pragma unroll
        for (int i = 0; i < 8; i++) r[i] = fmaxf(r[i], 0.0f);
    }
    if constexpr (std::is_same<OUTT, __half>::value) {
        __half2 p0 = __floats2half2_rn(r[0], r[1]);
        __half2 p1 = __floats2half2_rn(r[2], r[3]);
        __half2 p2 = __floats2half2_rn(r[4], r[5]);
        __half2 p3 = __floats2half2_rn(r[6], r[7]);
        uint4 u;
        u.x = *(uint32_t*)&p0; u.y = *(uint32_t*)&p1;
        u.z = *(uint32_t*)&p2; u.w = *(uint32_t*)&p3;
        *(uint4*)&out[(size_t)node * C + colb] = u;
    } else {
        *(float4*)&out[(size_t)node * C + colb]     = make_float4(r[0], r[1], r[2], r[3]);
        *(float4*)&out[(size_t)node * C + colb + 4] = make_float4(r[4], r[5], r[6], r[7]);
    }
}

// ---------------- driver ----------------
static inline int cdiv(long long a, long long b) { return (int)((a + b - 1) / b); }

extern "C" void kernel_launch(void* const* d_in, const int* in_sizes, int n_in,
                              void* d_out, int out_size) {
    const float* x  = (const float*)d_in[0];
    const float* W1 = (const float*)d_in[1];
    const float* b1 = (const float*)d_in[2];
    const float* W2 = (const float*)d_in[3];
    const float* b2 = (const float*)d_in[4];
    const float* W3 = (const float*)d_in[5];
    const float* b3 = (const float*)d_in[6];
    const int*   ei = (const int*)d_in[7];   // int32 (JAX default dtype demotion)
    int E = in_sizes[7] / 2;
    float* out = (float*)d_out;

    __half *h, *t, *xh, *w1h, *w2h, *w3h;
    cudaGetSymbolAddress((void**)&h,   g_h);
    cudaGetSymbolAddress((void**)&t,   g_t);
    cudaGetSymbolAddress((void**)&xh,  g_xh);
    cudaGetSymbolAddress((void**)&w1h, g_w1h);
    cudaGetSymbolAddress((void**)&w2h, g_w2h);
    cudaGetSymbolAddress((void**)&w3h, g_w3h);

    static cudaStream_t s2 = [] {
        cudaStream_t s; cudaStreamCreateWithFlags(&s, cudaStreamNonBlocking); return s;
    }();
    static cudaEvent_t eFork = [] {
        cudaEvent_t e; cudaEventCreateWithFlags(&e, cudaEventDisableTiming); return e;
    }();
    static cudaEvent_t eJoin = [] {
        cudaEvent_t e; cudaEventCreateWithFlags(&e, cudaEventDisableTiming); return e;
    }();

    const int TPB = 256;

    // ---- fork: graph prep + W2/W3 conversion on s2 ----
    cudaEventRecord(eFork, 0);
    cudaStreamWaitEvent(s2, eFork, 0);
    zero_fill_kernel<<<cdiv(N_NODES, TPB), TPB, 0, s2>>>();
    fill_kernel<<<cdiv(E, TPB), TPB, 0, s2>>>(ei, E);
    dis_kernel<<<cdiv(N_NODES, TPB), TPB, 0, s2>>>();
    cvt_kernel<<<cdiv(256 * 128 / 4, TPB), TPB, 0, s2>>>(W2, w2h, 256 * 128 / 4);
    cvt_kernel<<<cdiv(128 * 64 / 4, TPB), TPB, 0, s2>>>(W3, w3h, 128 * 64 / 4);
    cudaEventRecord(eJoin, s2);

    // ---- stream 0: convert gemm1 inputs ----
    cvt_kernel<<<cdiv(N_NODES * 256 / 4, TPB), TPB>>>(x, xh, N_NODES * 256 / 4);
    cvt_kernel<<<cdiv(256 * 256 / 4, TPB), TPB>>>(W1, w1h, 256 * 256 / 4);

    // ---- layer 1: 256 -> 256, relu ----
    {
        dim3 grid(256 / 64, cdiv(N_NODES, 128));
        gemm_f16_kernel<<<grid, 256>>>(xh, w1h, h, N_NODES, 256, 256);
        cudaStreamWaitEvent(0, eJoin, 0);
        aggregate_kernel<256, true, __half><<<cdiv(N_NODES, 4), 128>>>(h, b1, t);
    }
    // ---- layer 2: 256 -> 128, relu ----
    {
        dim3 grid(128 / 64, cdiv(N_NODES, 128));
        gemm_f16_kernel<<<grid, 256>>>(t, w2h, h, N_NODES, 128, 256);
        aggregate_kernel<128, true, __half><<<cdiv(N_NODES, 8), 128>>>(h, b2, t);
    }
    // ---- layer 3: 128 -> 64, no relu ----
    {
        dim3 grid(64 / 64, cdiv(N_NODES, 128));
        gemm_f16_kernel<<<grid, 256>>>(t, w3h, h, N_NODES, 64, 128);
        aggregate_kernel<64, false, float><<<cdiv(N_NODES, 16), 128>>>(h, b3, out);
    }
}

// round 16
// speedup vs baseline: 1.4606x; 1.0117x over previous
#include <cuda_runtime.h>
#include <cuda_fp16.h>
#include <cstdint>
#include <type_traits>

#define N_NODES 20000
#define HALF_N 10000
#define MAXC 256
#define SLOT_SHIFT 6               // 64 slots per node (max indeg; Poisson(16) tail ~e^-40)
#define SLOTS (1 << SLOT_SHIFT)

// ---------------- scratch ----------------
__device__ int    g_fill[N_NODES];                     // indeg after fill
__device__ float  g_dis[N_NODES];
__device__ int    g_slots[(size_t)N_NODES * SLOTS];    // src lists, fixed stride
__device__ __half g_h1[(size_t)N_NODES * MAXC];        // GEMM output, layers 1&3
__device__ __half g_h2[(size_t)N_NODES * MAXC];        // GEMM output, layer 2
__device__ __half g_t[(size_t)N_NODES * MAXC];         // layer activation (fp16)
__device__ __half g_xh[(size_t)N_NODES * MAXC];        // x converted to fp16
__device__ __half g_w1h[256 * 256];
__device__ __half g_w2h[256 * 128];
__device__ __half g_w3h[128 * 64];

// ---------------- prep ----------------
__global__ void zero_fill_kernel() {
    int i = blockIdx.x * blockDim.x + threadIdx.x;
    if (i < N_NODES) g_fill[i] = 0;
}

__global__ void fill_kernel(const int* __restrict__ ei, int E) {
    int e = blockIdx.x * blockDim.x + threadIdx.x;
    if (e < E) {
        int s = ei[e];
        int d = ei[E + e];
        int pos = atomicAdd(&g_fill[d], 1);
        g_slots[((size_t)d << SLOT_SHIFT) + pos] = s;
    }
}

__global__ void dis_kernel() {
    int i = blockIdx.x * blockDim.x + threadIdx.x;
    if (i < N_NODES) g_dis[i] = rsqrtf((float)g_fill[i] + 1.0f);   // +1 self-loop
}

// fp32 -> fp16, float4 granularity
__global__ void cvt_kernel(const float* __restrict__ in, __half* __restrict__ out, int n4) {
    int i = blockIdx.x * blockDim.x + threadIdx.x;
    if (i < n4) {
        float4 f = ((const float4*)in)[i];
        ((__half2*)out)[2 * i]     = __floats2half2_rn(f.x, f.y);
        ((__half2*)out)[2 * i + 1] = __floats2half2_rn(f.z, f.w);
    }
}

// ---------------- FP16 GEMM: cp.async + ldmatrix + m16n8k16 ----------------
__device__ __forceinline__ uint32_t smem_u32(const void* p) {
    return (uint32_t)__cvta_generic_to_shared(p);
}

#define LDSM_X4(r0, r1, r2, r3, addr)                                        \
    asm volatile("ldmatrix.sync.aligned.m8n8.x4.shared.b16 {%0,%1,%2,%3}, [%4];" \
                 : "=r"(r0), "=r"(r1), "=r"(r2), "=r"(r3) : "r"(addr))

#define LDSM_X4_T(r0, r1, r2, r3, addr)                                      \
    asm volatile("ldmatrix.sync.aligned.m8n8.x4.trans.shared.b16 {%0,%1,%2,%3}, [%4];" \
                 : "=r"(r0), "=r"(r1), "=r"(r2), "=r"(r3) : "r"(addr))

__global__ void gemm_f16_kernel(const __half* __restrict__ A, const __half* __restrict__ B,
                                __half* __restrict__ Ch, int M, int N, int K) {
    const int BM = 128, BN = 64, BK = 16;
    const int ASTRIDE = 24;   // halves per A row (48B) -> conflict-free ldmatrix
    const int BSTRIDE = 72;   // halves per B k-row (144B) -> conflict-free ldmatrix.trans
    __shared__ __half As[2][BM][ASTRIDE];
    __shared__ __half Bs[2][BK][BSTRIDE];
    const int ABUF = BM * ASTRIDE * 2;
    const int BBUF = BK * BSTRIDE * 2;

    int tid = threadIdx.x;
    int lane = tid & 31;
    int wid = tid >> 5;
    int warp_m = wid & 3;
    int warp_n = wid >> 2;
    int brow = blockIdx.y * BM;
    int bcol = blockIdx.x * BN;

    int am = tid >> 1, aj = tid & 1;                // A: 16B per thread
    int bk = tid >> 4, bc = tid & 15;               // B: 8B per thread
    int agr = brow + am;
    const __half* aSrcBase = A + (size_t)agr * K + aj * 8;
    const __half* bSrcBase = B + (size_t)bk * N + bcol + bc * 4;
    uint32_t aDst = smem_u32(&As[0][0][0]) + am * 48 + aj * 16;
    uint32_t bDst = smem_u32(&Bs[0][0][0]) + bk * 144 + bc * 8;
    int aValid = (agr < M) ? 16 : 0;

    float acc[2][4][4];
    #pragma unroll
    for (int i = 0; i < 2; i++)
        #pragma unroll
        for (int j = 0; j < 4; j++)
            #pragma unroll
            for (int q = 0; q < 4; q++) acc[i][j][q] = 0.0f;

    int l15 = lane & 15;
    int lhi = lane >> 4;
    uint32_t sA = smem_u32(&As[0][0][0]);
    uint32_t sB = smem_u32(&Bs[0][0][0]);
    uint32_t aoff[2], boff[2];
    #pragma unroll
    for (int mt = 0; mt < 2; mt++)
        aoff[mt] = sA + (uint32_t)(((warp_m * 32 + mt * 16 + l15) * ASTRIDE + lhi * 8) * 2);
    #pragma unroll
    for (int p = 0; p < 2; p++)
        boff[p] = sB + (uint32_t)((l15 * BSTRIDE + warp_n * 32 + p * 16 + lhi * 8) * 2);

    auto issue = [&](int kt) {
        int k0 = kt * BK;
        uint32_t ad = aDst + (kt & 1) * ABUF;
        uint32_t bd = bDst + (kt & 1) * BBUF;
        asm volatile("cp.async.cg.shared.global [%0], [%1], 16, %2;"
                     :: "r"(ad), "l"(aSrcBase + k0), "r"(aValid));
        asm volatile("cp.async.ca.shared.global [%0], [%1], 8;"
                     :: "r"(bd), "l"(bSrcBase + (size_t)k0 * N));
        asm volatile("cp.async.commit_group;");
    };

    issue(0);

    int KT = K / BK;
    int cur = 0;
    for (int kt = 0; kt < KT; kt++) {
        bool more = (kt + 1 < KT);
        if (more) issue(kt + 1);
        if (more) asm volatile("cp.async.wait_group 1;");
        else      asm volatile("cp.async.wait_group 0;");
        __syncthreads();

        uint32_t a[2][4], b[2][4];
        uint32_t bufA = cur * ABUF, bufB = cur * BBUF;
        #pragma unroll
        for (int mt = 0; mt < 2; mt++)
            LDSM_X4(a[mt][0], a[mt][1], a[mt][2], a[mt][3], aoff[mt] + bufA);
        #pragma unroll
        for (int p = 0; p < 2; p++)
            LDSM_X4_T(b[p][0], b[p][1], b[p][2], b[p][3], boff[p] + bufB);

        #pragma unroll
        for (int mt = 0; mt < 2; mt++)
            #pragma unroll
            for (int nt = 0; nt < 4; nt++) {
                uint32_t b0 = b[nt >> 1][(nt & 1) * 2];
                uint32_t b1 = b[nt >> 1][(nt & 1) * 2 + 1];
                asm volatile(
                    "mma.sync.aligned.m16n8k16.row.col.f32.f16.f16.f32 "
                    "{%0,%1,%2,%3}, {%4,%5,%6,%7}, {%8,%9}, {%0,%1,%2,%3};"
                    : "+f"(acc[mt][nt][0]), "+f"(acc[mt][nt][1]),
                      "+f"(acc[mt][nt][2]), "+f"(acc[mt][nt][3])
                    : "r"(a[mt][0]), "r"(a[mt][1]), "r"(a[mt][2]), "r"(a[mt][3]),
                      "r"(b0), "r"(b1));
            }

        if (more) __syncthreads();
        cur ^= 1;
    }

    int g = lane >> 2;
    int tg = lane & 3;
    #pragma unroll
    for (int mt = 0; mt < 2; mt++) {
        int r0 = brow + warp_m * 32 + mt * 16 + g;
        int r1 = r0 + 8;
        #pragma unroll
        for (int nt = 0; nt < 4; nt++) {
            int cc = bcol + warp_n * 32 + nt * 8 + 2 * tg;
            if (r0 < M) {
                __half2 v = __floats2half2_rn(acc[mt][nt][0], acc[mt][nt][1]);
                *(__half2*)&Ch[(size_t)r0 * N + cc] = v;
            }
            if (r1 < M) {
                __half2 v = __floats2half2_rn(acc[mt][nt][2], acc[mt][nt][3]);
                *(__half2*)&Ch[(size_t)r1 * N + cc] = v;
            }
        }
    }
}

// ---------------- fused aggregate + self-loop + bias (+relu), node-chunked ----------------
__device__ __forceinline__ void fma8(float* acc, uint4 v, float w) {
    float2 f0 = __half22float2(*(__half2*)&v.x);
    float2 f1 = __half22float2(*(__half2*)&v.y);
    float2 f2 = __half22float2(*(__half2*)&v.z);
    float2 f3 = __half22float2(*(__half2*)&v.w);
    acc[0] = fmaf(f0.x, w, acc[0]); acc[1] = fmaf(f0.y, w, acc[1]);
    acc[2] = fmaf(f1.x, w, acc[2]); acc[3] = fmaf(f1.y, w, acc[3]);
    acc[4] = fmaf(f2.x, w, acc[4]); acc[5] = fmaf(f2.y, w, acc[5]);
    acc[6] = fmaf(f3.x, w, acc[6]); acc[7] = fmaf(f3.y, w, acc[7]);
}

template<int C, bool RELU, typename OUTT>
__global__ void aggregate_kernel(const __half* __restrict__ h,
                                 const float* __restrict__ bias,
                                 OUTT* __restrict__ out, int node0, int nnodes) {
    constexpr int TPN = C / 8;
    constexpr int NPB = 128 / TPN;
    int local = threadIdx.x / TPN;
    int c8 = threadIdx.x % TPN;
    int node = node0 + blockIdx.x * NPB + local;
    if (node >= node0 + nnodes) return;

    const uint4* h8 = (const uint4*)h;
    const size_t S = C / 8;
    int indeg = __ldg(&g_fill[node]);
    float d = rsqrtf((float)indeg + 1.0f);

    float acc[8] = {};
    fma8(acc, __ldg(&h8[(size_t)node * S + c8]), d);   // self-loop

    const int* slots = &g_slots[(size_t)node << SLOT_SHIFT];
    int p = 0;
    for (; p + 4 <= indeg; p += 4) {
        int s0 = __ldg(&slots[p]),     s1 = __ldg(&slots[p + 1]);
        int s2 = __ldg(&slots[p + 2]), s3 = __ldg(&slots[p + 3]);
        float w0 = __ldg(&g_dis[s0]),  w1 = __ldg(&g_dis[s1]);
        float w2 = __ldg(&g_dis[s2]),  w3 = __ldg(&g_dis[s3]);
        uint4 v0 = __ldg(&h8[(size_t)s0 * S + c8]);
        uint4 v1 = __ldg(&h8[(size_t)s1 * S + c8]);
        uint4 v2 = __ldg(&h8[(size_t)s2 * S + c8]);
        uint4 v3 = __ldg(&h8[(size_t)s3 * S + c8]);
        fma8(acc, v0, w0); fma8(acc, v1, w1); fma8(acc, v2, w2); fma8(acc, v3, w3);
    }
    for (; p < indeg; ++p) {
        int s = __ldg(&slots[p]);
        fma8(acc, __ldg(&h8[(size_t)s * S + c8]), __ldg(&g_dis[s]));
    }

    int colb = c8 * 8;
    float4 b0 = __ldg(&((const float4*)bias)[c8 * 2]);
    float4 b1 = __ldg(&((const float4*)bias)[c8 * 2 + 1]);
    float r[8];
    r[0] = fmaf(d, acc[0], b0.x); r[1] = fmaf(d, acc[1], b0.y);
    r[2] = fmaf(d, acc[2], b0.z); r[3] = fmaf(d, acc[3], b0.w);
    r[4] = fmaf(d, acc[4], b1.x); r[5] = fmaf(d, acc[5], b1.y);
    r[6] = fmaf(d, acc[6], b1.z); r[7] = fmaf(d, acc[7], b1.w);
    if (RELU) {
        #pragma unroll
        for (int i = 0; i < 8; i++) r[i] = fmaxf(r[i], 0.0f);
    }
    if constexpr (std::is_same<OUTT, __half>::value) {
        __half2 p0 = __floats2half2_rn(r[0], r[1]);
        __half2 p1 = __floats2half2_rn(r[2], r[3]);
        __half2 p2 = __floats2half2_rn(r[4], r[5]);
        __half2 p3 = __floats2half2_rn(r[6], r[7]);
        uint4 u;
        u.x = *(uint32_t*)&p0; u.y = *(uint32_t*)&p1;
        u.z = *(uint32_t*)&p2; u.w = *(uint32_t*)&p3;
        *(uint4*)&out[(size_t)node * C + colb] = u;
    } else {
        *(float4*)&out[(size_t)node * C + colb]     = make_float4(r[0], r[1], r[2], r[3]);
        *(float4*)&out[(size_t)node * C + colb + 4] = make_float4(r[4], r[5], r[6], r[7]);
    }
}

// ---------------- driver ----------------
static inline int cdiv(long long a, long long b) { return (int)((a + b - 1) / b); }

static cudaEvent_t make_event() {
    cudaEvent_t e;
    cudaEventCreateWithFlags(&e, cudaEventDisableTiming);
    return e;
}

extern "C" void kernel_launch(void* const* d_in, const int* in_sizes, int n_in,
                              void* d_out, int out_size) {
    const float* x  = (const float*)d_in[0];
    const float* W1 = (const float*)d_in[1];
    const float* b1 = (const float*)d_in[2];
    const float* W2 = (const float*)d_in[3];
    const float* b2 = (const float*)d_in[4];
    const float* W3 = (const float*)d_in[5];
    const float* b3 = (const float*)d_in[6];
    const int*   ei = (const int*)d_in[7];   // int32 (JAX default dtype demotion)
    int E = in_sizes[7] / 2;
    float* out = (float*)d_out;

    __half *h1, *h2, *t, *xh, *w1h, *w2h, *w3h;
    cudaGetSymbolAddress((void**)&h1,  g_h1);
    cudaGetSymbolAddress((void**)&h2,  g_h2);
    cudaGetSymbolAddress((void**)&t,   g_t);
    cudaGetSymbolAddress((void**)&xh,  g_xh);
    cudaGetSymbolAddress((void**)&w1h, g_w1h);
    cudaGetSymbolAddress((void**)&w2h, g_w2h);
    cudaGetSymbolAddress((void**)&w3h, g_w3h);

    // infrastructure handles (created on the eager correctness call, not during capture)
    static cudaStream_t s2 = [] {
        cudaStream_t s; cudaStreamCreateWithFlags(&s, cudaStreamNonBlocking); return s;
    }();
    static cudaEvent_t eFork = make_event();
    static cudaEvent_t eJoin = make_event();
    static cudaEvent_t eG1   = make_event();
    static cudaEvent_t eC0   = make_event();
    static cudaEvent_t eC1   = make_event();
    static cudaEvent_t eD0   = make_event();
    static cudaEvent_t eD1   = make_event();
    static cudaEvent_t eE    = make_event();

    const int TPB = 256;
    const int H = HALF_N;

    // ---- fork: graph prep + W2/W3 conversion on s2 ----
    cudaEventRecord(eFork, 0);
    cudaStreamWaitEvent(s2, eFork, 0);
    zero_fill_kernel<<<cdiv(N_NODES, TPB), TPB, 0, s2>>>();
    fill_kernel<<<cdiv(E, TPB), TPB, 0, s2>>>(ei, E);
    dis_kernel<<<cdiv(N_NODES, TPB), TPB, 0, s2>>>();
    cvt_kernel<<<cdiv(256 * 128 / 4, TPB), TPB, 0, s2>>>(W2, w2h, 256 * 128 / 4);
    cvt_kernel<<<cdiv(128 * 64 / 4, TPB), TPB, 0, s2>>>(W3, w3h, 128 * 64 / 4);
    cudaEventRecord(eJoin, s2);

    // ---- stream 0: convert gemm1 inputs, gemm1 (all rows) ----
    cvt_kernel<<<cdiv(N_NODES * 256 / 4, TPB), TPB>>>(x, xh, N_NODES * 256 / 4);
    cvt_kernel<<<cdiv(256 * 256 / 4, TPB), TPB>>>(W1, w1h, 256 * 256 / 4);
    {
        dim3 grid(256 / 64, cdiv(N_NODES, 128));
        gemm_f16_kernel<<<grid, 256>>>(xh, w1h, h1, N_NODES, 256, 256);
    }
    cudaEventRecord(eG1, 0);
    cudaStreamWaitEvent(0, eJoin, 0);

    // ---- pipelined layers: chunk 0 on stream 0, chunk 1 on s2 ----
    // layer 1 agg -> layer 2 gemm
    aggregate_kernel<256, true, __half><<<cdiv(H, 4), 128>>>(h1, b1, t, 0, H);
    {
        dim3 grid(128 / 64, cdiv(H, 128));
        gemm_f16_kernel<<<grid, 256>>>(t, w2h, h2, H, 128, 256);
    }
    cudaEventRecord(eC0, 0);

    cudaStreamWaitEvent(s2, eG1, 0);
    aggregate_kernel<256, true, __half><<<cdiv(H, 4), 128, 0, s2>>>(h1, b1, t, H, H);
    {
        dim3 grid(128 / 64, cdiv(H, 128));
        gemm_f16_kernel<<<grid, 256, 0, s2>>>(t + (size_t)H * 256, w2h,
                                              h2 + (size_t)H * 128, H, 128, 256);
    }
    cudaEventRecord(eC1, s2);

    // layer 2 agg -> layer 3 gemm
    cudaStreamWaitEvent(0, eC1, 0);
    aggregate_kernel<128, true, __half><<<cdiv(H, 8), 128>>>(h2, b2, t, 0, H);
    {
        dim3 grid(64 / 64, cdiv(H, 128));
        gemm_f16_kernel<<<grid, 256>>>(t, w3h, h1, H, 64, 128);
    }
    cudaEventRecord(eD0, 0);

    cudaStreamWaitEvent(s2, eC0, 0);
    aggregate_kernel<128, true, __half><<<cdiv(H, 8), 128, 0, s2>>>(h2, b2, t, H, H);
    {
        dim3 grid(64 / 64, cdiv(H, 128));
        gemm_f16_kernel<<<grid, 256, 0, s2>>>(t + (size_t)H * 128, w3h,
                                              h1 + (size_t)H * 64, H, 64, 128);
    }
    cudaEventRecord(eD1, s2);

    // layer 3 agg (final, fp32 out)
    cudaStreamWaitEvent(0, eD1, 0);
    aggregate_kernel<64, false, float><<<cdiv(H, 16), 128>>>(h1, b3, out, 0, H);

    cudaStreamWaitEvent(s2, eD0, 0);
    aggregate_kernel<64, false, float><<<cdiv(H, 16), 128, 0, s2>>>(h1, b3, out, H, H);
    cudaEventRecord(eE, s2);
    cudaStreamWaitEvent(0, eE, 0);
}